// round 6
// baseline (speedup 1.0000x reference)
#include <cuda_runtime.h>
#include <cuda_bf16.h>
#include <cstdint>
#include <cmath>

#define BB   64      // batch
#define TT   1024    // timesteps
#define DD   512     // input dim
#define HH   512     // hidden dim
#define G4   2048    // 4*H
#define NBLK 128     // persistent blocks

// ---------------- scratch ----------------
__device__ float g_xp[(size_t)TT * BB * G4];   // [T][B][4H]
__device__ float g_h[2][(size_t)BB * HH];      // double-buffered h
__device__ unsigned int g_bar;

// =====================================================================
// Phase 1: xproj GEMM (proven version, unchanged).
// =====================================================================
__global__ void __launch_bounds__(256) xproj_gemm(
    const float* __restrict__ x,
    const float* __restrict__ Wc, const float* __restrict__ Wi,
    const float* __restrict__ Wf, const float* __restrict__ Wo,
    const float* __restrict__ bc, const float* __restrict__ bi,
    const float* __restrict__ bf, const float* __restrict__ bo)
{
    __shared__ float As[16][68];
    __shared__ float Bs[16][64];

    const int tid = threadIdx.x;
    const int n0  = blockIdx.x * 64;
    const int g   = n0 >> 9;
    const int col0 = n0 & 511;
    const int m0  = blockIdx.y * 64;

    const float* Wg = (g == 0) ? Wc : (g == 1) ? Wi : (g == 2) ? Wf : Wo;
    const float* bg = (g == 0) ? bc : (g == 1) ? bi : (g == 2) ? bf : bo;

    const int tx = tid & 15;
    const int ty = tid >> 4;

    float acc[4][4];
#pragma unroll
    for (int u = 0; u < 4; u++)
#pragma unroll
        for (int v = 0; v < 4; v++) acc[u][v] = 0.f;

    const int arow = tid >> 2;
    const int akq  = tid & 3;
    const int bkr  = tid >> 4;
    const int bnq  = tid & 15;

    for (int k0 = 0; k0 < DD; k0 += 16) {
        {
            const float4 v = *reinterpret_cast<const float4*>(
                x + (size_t)(m0 + arow) * DD + k0 + akq * 4);
            As[akq * 4 + 0][arow] = v.x;
            As[akq * 4 + 1][arow] = v.y;
            As[akq * 4 + 2][arow] = v.z;
            As[akq * 4 + 3][arow] = v.w;
        }
        {
            const float4 v = *reinterpret_cast<const float4*>(
                Wg + (size_t)(k0 + bkr) * HH + col0 + bnq * 4);
            *reinterpret_cast<float4*>(&Bs[bkr][bnq * 4]) = v;
        }
        __syncthreads();
#pragma unroll
        for (int kk = 0; kk < 16; kk++) {
            const float4 a4 = *reinterpret_cast<const float4*>(&As[kk][ty * 4]);
            const float4 b4 = *reinterpret_cast<const float4*>(&Bs[kk][tx * 4]);
            const float av[4] = {a4.x, a4.y, a4.z, a4.w};
            const float bv[4] = {b4.x, b4.y, b4.z, b4.w};
#pragma unroll
            for (int u = 0; u < 4; u++)
#pragma unroll
                for (int v = 0; v < 4; v++)
                    acc[u][v] = fmaf(av[u], bv[v], acc[u][v]);
        }
        __syncthreads();
    }

    const float4 bb4 = *reinterpret_cast<const float4*>(bg + col0 + tx * 4);
#pragma unroll
    for (int u = 0; u < 4; u++) {
        const int r  = m0 + ty * 4 + u;
        const int b_ = r >> 10;
        const int t_ = r & 1023;
        float4 o;
        o.x = acc[u][0] + bb4.x;
        o.y = acc[u][1] + bb4.y;
        o.z = acc[u][2] + bb4.z;
        o.w = acc[u][3] + bb4.w;
        *reinterpret_cast<float4*>(
            g_xp + ((size_t)t_ * BB + b_) * G4 + g * HH + col0 + tx * 4) = o;
    }
}

// =====================================================================
// Phase 2: persistent recurrence, 256 threads, 4-way k-split,
// packed fma.rn.f32x2 over k-pairs.
// 128 blocks = 4 batch-groups(16) x 32 j-groups(16 cols x 4 gates).
// smem: Us2[256 kp][64 c] float2 (k-pairs), hs2[256 kp][HSP2] float2,
//       Cmb[4 quarter][16 b][68] float.
// Thread (kq, tyl, txl): 4b x 4c microtile over 64 kp; lo lane = even k,
// hi lane = odd k; summed at the end (exact reordering).
// =====================================================================
#define THR     256
#define HSP2    18                       // hs2 pitch in float2
#define CMBP    68
#define SMEM_BYTES (256*64*8 + 256*HSP2*8 + 4*16*CMBP*4)   // 185,344

__device__ __forceinline__ float sigf(float v) {
    return 1.f / (1.f + __expf(-v));
}

__device__ __forceinline__ void ffma2(unsigned long long& d,
                                      unsigned long long a,
                                      unsigned long long b) {
    asm("fma.rn.f32x2 %0, %1, %2, %0;" : "+l"(d) : "l"(a), "l"(b));
}

__device__ __forceinline__ float f2sum(unsigned long long v) {
    const float lo = __uint_as_float((unsigned)(v & 0xFFFFFFFFull));
    const float hi = __uint_as_float((unsigned)(v >> 32));
    return lo + hi;
}

__global__ void __launch_bounds__(THR, 1) lstm_recur(
    const float* __restrict__ Uc, const float* __restrict__ Ui,
    const float* __restrict__ Uf, const float* __restrict__ Uo,
    float* __restrict__ out)
{
    extern __shared__ float2 sm2[];
    float2* Us2 = sm2;                          // [256][64]
    float2* hs2 = sm2 + 256 * 64;               // [256][HSP2]
    float*  Cmb = reinterpret_cast<float*>(hs2 + 256 * HSP2);  // [4][16][68]

    const int tid  = threadIdx.x;
    const int bx   = blockIdx.x;
    const int b0   = (bx >> 5) * 16;
    const int jcol0 = (bx & 31) * 16;

    // ---- load resident U slice, k-paired: Us2[kp][c] = {U(2kp), U(2kp+1)} ----
    {
        const int c4   = tid & 15;
        const int gate = c4 >> 2;
        const float* Ug = (gate == 0) ? Uc : (gate == 1) ? Ui
                        : (gate == 2) ? Uf : Uo;
        const float* src = Ug + jcol0 + (c4 & 3) * 4;
        for (int kp = tid >> 4; kp < 256; kp += 16) {
            const float4 a = *reinterpret_cast<const float4*>(src + (size_t)(2 * kp) * HH);
            const float4 b = *reinterpret_cast<const float4*>(src + (size_t)(2 * kp + 1) * HH);
            float2* dst = Us2 + kp * 64 + c4 * 4;
            dst[0] = make_float2(a.x, b.x);
            dst[1] = make_float2(a.y, b.y);
            dst[2] = make_float2(a.z, b.z);
            dst[3] = make_float2(a.w, b.w);
        }
    }

    // microtile identity: kq = k-quarter, (tyl, txl) within quarter
    const int kq  = tid >> 6;          // 0..3
    const int lcl = tid & 63;
    const int txl = lcl & 15;          // 4 cols: txl*4..+3
    const int tyl = lcl >> 4;          // 4 batches: tyl*4..+3
    const int kp0 = kq * 64;

    // staging identity
    const int sb = tid & 15;
    const int sq = tid >> 4;           // 0..15

    // gate identity: one (b, j) pair per thread
    const int gjb   = tid >> 4;        // 0..15
    const int gj    = tid & 15;
    const int gb    = b0 + gjb;
    const int jglob = jcol0 + gj;

    float cst = 0.f;

    __syncthreads();

    for (int t = 0; t < TT; t++) {
        const float* xp = g_xp + ((size_t)t * BB + gb) * G4 + jglob;
        const float xc = xp[0];
        const float xi = xp[HH];
        const float xf = xp[2 * HH];
        const float xo = xp[3 * HH];

        float sc = 0.f, si = 0.f, sf = 0.f, so = 0.f;

        if (t > 0) {
            // ---- stage h(t-1), k-paired transposed: hs2[kp][b] ----
            const float* hb = g_h[t & 1] + (size_t)(b0 + sb) * HH;
#pragma unroll
            for (int it = 0; it < 8; it++) {
                const int kb = (sq + it * 16) * 4;          // k, multiple of 4
                const float4 v = __ldcg(reinterpret_cast<const float4*>(hb + kb));
                const int kp = kb >> 1;
                hs2[(kp + 0) * HSP2 + sb] = make_float2(v.x, v.y);
                hs2[(kp + 1) * HSP2 + sb] = make_float2(v.z, v.w);
            }
            __syncthreads();

            unsigned long long acc[4][4];
#pragma unroll
            for (int i = 0; i < 4; i++)
#pragma unroll
                for (int j = 0; j < 4; j++) acc[i][j] = 0ull;

#pragma unroll 4
            for (int kp = kp0; kp < kp0 + 64; kp++) {
                const ulonglong2 h01 = *reinterpret_cast<const ulonglong2*>(
                    hs2 + kp * HSP2 + tyl * 4);
                const ulonglong2 h23 = *reinterpret_cast<const ulonglong2*>(
                    hs2 + kp * HSP2 + tyl * 4 + 2);
                const ulonglong2 u01 = *reinterpret_cast<const ulonglong2*>(
                    Us2 + kp * 64 + txl * 4);
                const ulonglong2 u23 = *reinterpret_cast<const ulonglong2*>(
                    Us2 + kp * 64 + txl * 4 + 2);
                const unsigned long long hv[4] = {h01.x, h01.y, h23.x, h23.y};
                const unsigned long long uv[4] = {u01.x, u01.y, u23.x, u23.y};
#pragma unroll
                for (int i = 0; i < 4; i++)
#pragma unroll
                    for (int j = 0; j < 4; j++)
                        ffma2(acc[i][j], hv[i], uv[j]);
            }

            // ---- write quarter partials (lo+hi summed) ----
            {
                float4* Cq = reinterpret_cast<float4*>(Cmb + kq * 16 * CMBP);
#pragma unroll
                for (int i = 0; i < 4; i++)
                    Cq[(tyl * 4 + i) * 17 + txl] =
                        make_float4(f2sum(acc[i][0]), f2sum(acc[i][1]),
                                    f2sum(acc[i][2]), f2sum(acc[i][3]));
            }
            __syncthreads();

            // ---- gate threads sum 4 quarters ----
            const float* Cb = Cmb + gjb * CMBP + gj;
#pragma unroll
            for (int q = 0; q < 4; q++) {
                const float* Cq = Cb + q * 16 * CMBP;
                sc += Cq[0];
                si += Cq[16];
                sf += Cq[32];
                so += Cq[48];
            }
        }

        // ---- gate math (1 pair / thread), c-state in register ----
        {
            const float a  = tanhf(xc + sc);
            const float ig = sigf(xi + si);
            const float fg = sigf(xf + sf);
            const float og = sigf(xo + so);
            cst = ig * a + fg * cst;
            const float hval = og * tanhf(cst);
            out[((size_t)gb * TT + t) * HH + jglob] = hval;
            g_h[(t + 1) & 1][(size_t)gb * HH + jglob] = hval;
        }

        // ---- grid barrier (proven volatile spin) ----
        __threadfence();
        __syncthreads();
        if (tid == 0) {
            atomicAdd(&g_bar, 1u);
            const unsigned tgt = (unsigned)(t + 1) * (unsigned)NBLK;
            while (*reinterpret_cast<volatile unsigned*>(&g_bar) < tgt) { }
        }
        __syncthreads();
    }
}

// =====================================================================
extern "C" void kernel_launch(void* const* d_in, const int* in_sizes, int n_in,
                              void* d_out, int out_size)
{
    const float* x  = (const float*)d_in[0];
    const float* Wc = (const float*)d_in[1];
    const float* Wi = (const float*)d_in[2];
    const float* Wf = (const float*)d_in[3];
    const float* Wo = (const float*)d_in[4];
    const float* Uc = (const float*)d_in[5];
    const float* Ui = (const float*)d_in[6];
    const float* Uf = (const float*)d_in[7];
    const float* Uo = (const float*)d_in[8];
    const float* bc = (const float*)d_in[9];
    const float* bi = (const float*)d_in[10];
    const float* bf = (const float*)d_in[11];
    const float* bo = (const float*)d_in[12];
    float* out = (float*)d_out;

    cudaFuncSetAttribute(lstm_recur,
                         cudaFuncAttributeMaxDynamicSharedMemorySize, SMEM_BYTES);

    void* barp = nullptr;
    cudaGetSymbolAddress(&barp, g_bar);
    cudaMemsetAsync(barp, 0, sizeof(unsigned int), 0);

    dim3 g1(G4 / 64, (BB * TT) / 64);   // 32 x 1024
    xproj_gemm<<<g1, 256>>>(x, Wc, Wi, Wf, Wo, bc, bi, bf, bo);

    lstm_recur<<<NBLK, THR, SMEM_BYTES>>>(Uc, Ui, Uf, Uo, out);
}

// round 7
// speedup vs baseline: 1.0332x; 1.0332x over previous
#include <cuda_runtime.h>
#include <cuda_bf16.h>
#include <cstdint>
#include <cmath>

#define BB   64      // batch
#define TT   1024    // timesteps
#define DD   512     // input dim
#define HH   512     // hidden dim
#define G4   2048    // 4*H
#define NBLK 128     // persistent blocks

// ---------------- scratch ----------------
__device__ float g_xp[(size_t)TT * BB * G4];   // [T][B][4H]
__device__ float g_h[2][(size_t)BB * HH];      // double-buffered h
__device__ unsigned int g_bar;

// =====================================================================
// Phase 1: xproj GEMM (proven version, unchanged).
// =====================================================================
__global__ void __launch_bounds__(256) xproj_gemm(
    const float* __restrict__ x,
    const float* __restrict__ Wc, const float* __restrict__ Wi,
    const float* __restrict__ Wf, const float* __restrict__ Wo,
    const float* __restrict__ bc, const float* __restrict__ bi,
    const float* __restrict__ bf, const float* __restrict__ bo)
{
    __shared__ float As[16][68];
    __shared__ float Bs[16][64];

    const int tid = threadIdx.x;
    const int n0  = blockIdx.x * 64;
    const int g   = n0 >> 9;
    const int col0 = n0 & 511;
    const int m0  = blockIdx.y * 64;

    const float* Wg = (g == 0) ? Wc : (g == 1) ? Wi : (g == 2) ? Wf : Wo;
    const float* bg = (g == 0) ? bc : (g == 1) ? bi : (g == 2) ? bf : bo;

    const int tx = tid & 15;
    const int ty = tid >> 4;

    float acc[4][4];
#pragma unroll
    for (int u = 0; u < 4; u++)
#pragma unroll
        for (int v = 0; v < 4; v++) acc[u][v] = 0.f;

    const int arow = tid >> 2;
    const int akq  = tid & 3;
    const int bkr  = tid >> 4;
    const int bnq  = tid & 15;

    for (int k0 = 0; k0 < DD; k0 += 16) {
        {
            const float4 v = *reinterpret_cast<const float4*>(
                x + (size_t)(m0 + arow) * DD + k0 + akq * 4);
            As[akq * 4 + 0][arow] = v.x;
            As[akq * 4 + 1][arow] = v.y;
            As[akq * 4 + 2][arow] = v.z;
            As[akq * 4 + 3][arow] = v.w;
        }
        {
            const float4 v = *reinterpret_cast<const float4*>(
                Wg + (size_t)(k0 + bkr) * HH + col0 + bnq * 4);
            *reinterpret_cast<float4*>(&Bs[bkr][bnq * 4]) = v;
        }
        __syncthreads();
#pragma unroll
        for (int kk = 0; kk < 16; kk++) {
            const float4 a4 = *reinterpret_cast<const float4*>(&As[kk][ty * 4]);
            const float4 b4 = *reinterpret_cast<const float4*>(&Bs[kk][tx * 4]);
            const float av[4] = {a4.x, a4.y, a4.z, a4.w};
            const float bv[4] = {b4.x, b4.y, b4.z, b4.w};
#pragma unroll
            for (int u = 0; u < 4; u++)
#pragma unroll
                for (int v = 0; v < 4; v++)
                    acc[u][v] = fmaf(av[u], bv[v], acc[u][v]);
        }
        __syncthreads();
    }

    const float4 bb4 = *reinterpret_cast<const float4*>(bg + col0 + tx * 4);
#pragma unroll
    for (int u = 0; u < 4; u++) {
        const int r  = m0 + ty * 4 + u;
        const int b_ = r >> 10;
        const int t_ = r & 1023;
        float4 o;
        o.x = acc[u][0] + bb4.x;
        o.y = acc[u][1] + bb4.y;
        o.z = acc[u][2] + bb4.z;
        o.w = acc[u][3] + bb4.w;
        *reinterpret_cast<float4*>(
            g_xp + ((size_t)t_ * BB + b_) * G4 + g * HH + col0 + tx * 4) = o;
    }
}

// =====================================================================
// Phase 2: persistent recurrence.
// 256 threads, 4-way k-split (round-6 proven schedule) with plain
// scalar FFMA and float smem layouts (round-5 proven arithmetic).
// 128 blocks = 4 batch-groups(16) x 32 j-groups(16 cols x 4 gates).
// smem: Us[512][64] k-major, hs[512][HSP] transposed h, Cmb[4][16][68].
// Thread (kq, tyl, txl): 4b x 4c microtile over 128 k.
// =====================================================================
#define THR     256
#define HSP     20
#define CMBP    68
#define SMEM_BYTES ((512*64 + 512*HSP + 4*16*CMBP) * 4)   // 189,440

__device__ __forceinline__ float sigf(float v) {
    return 1.f / (1.f + __expf(-v));
}

__global__ void __launch_bounds__(THR, 1) lstm_recur(
    const float* __restrict__ Uc, const float* __restrict__ Ui,
    const float* __restrict__ Uf, const float* __restrict__ Uo,
    float* __restrict__ out)
{
    extern __shared__ float sm[];
    float* Us  = sm;                    // [512][64]
    float* hs  = sm + 512 * 64;         // [512][HSP]
    float* Cmb = hs + 512 * HSP;        // [4][16][CMBP]

    const int tid  = threadIdx.x;
    const int bx   = blockIdx.x;
    const int b0   = (bx >> 5) * 16;
    const int jcol0 = (bx & 31) * 16;

    // ---- load resident U slice: Us[k][gate*16+jc] ----
    {
        const int c4   = tid & 15;
        const int gate = c4 >> 2;
        const float* Ug = (gate == 0) ? Uc : (gate == 1) ? Ui
                        : (gate == 2) ? Uf : Uo;
        const float* src = Ug + jcol0 + (c4 & 3) * 4;
        for (int k = tid >> 4; k < 512; k += 16)
            *reinterpret_cast<float4*>(&Us[k * 64 + c4 * 4]) =
                *reinterpret_cast<const float4*>(src + (size_t)k * HH);
    }

    // microtile identity
    const int kq  = tid >> 6;          // k-quarter 0..3
    const int lcl = tid & 63;
    const int txl = lcl & 15;          // 4 cols: txl*4..+3
    const int tyl = lcl >> 4;          // 4 batches: tyl*4..+3
    const int k0q = kq * 128;

    // staging identity
    const int sb = tid & 15;
    const int sq = tid >> 4;           // 0..15

    // gate identity: one (b, j) pair per thread
    const int gjb   = tid >> 4;        // 0..15
    const int gj    = tid & 15;
    const int gb    = b0 + gjb;
    const int jglob = jcol0 + gj;

    const float4* Us4 = reinterpret_cast<const float4*>(Us);

    float cst = 0.f;

    __syncthreads();

    for (int t = 0; t < TT; t++) {
        const float* xp = g_xp + ((size_t)t * BB + gb) * G4 + jglob;
        const float xc = xp[0];
        const float xi = xp[HH];
        const float xf = xp[2 * HH];
        const float xo = xp[3 * HH];

        float sc = 0.f, si = 0.f, sf = 0.f, so = 0.f;

        if (t > 0) {
            // ---- stage h(t-1) transposed: hs[k][b] ----
            const float* hb = g_h[t & 1] + (size_t)(b0 + sb) * HH;
#pragma unroll
            for (int it = 0; it < 8; it++) {
                const int kb = (sq + it * 16) * 4;
                const float4 v = __ldcg(reinterpret_cast<const float4*>(hb + kb));
                hs[(kb + 0) * HSP + sb] = v.x;
                hs[(kb + 1) * HSP + sb] = v.y;
                hs[(kb + 2) * HSP + sb] = v.z;
                hs[(kb + 3) * HSP + sb] = v.w;
            }
            __syncthreads();

            float acc[4][4];
#pragma unroll
            for (int i = 0; i < 4; i++)
#pragma unroll
                for (int j = 0; j < 4; j++) acc[i][j] = 0.f;

#pragma unroll 4
            for (int k = k0q; k < k0q + 128; k++) {
                const float4 hv = *reinterpret_cast<const float4*>(
                    &hs[k * HSP + tyl * 4]);
                const float4 uv = Us4[k * 16 + txl];
                const float av[4] = {hv.x, hv.y, hv.z, hv.w};
                const float bv[4] = {uv.x, uv.y, uv.z, uv.w};
#pragma unroll
                for (int i = 0; i < 4; i++)
#pragma unroll
                    for (int j = 0; j < 4; j++)
                        acc[i][j] = fmaf(av[i], bv[j], acc[i][j]);
            }

            // ---- write quarter partials ----
            {
                float4* Cq = reinterpret_cast<float4*>(Cmb + kq * 16 * CMBP);
#pragma unroll
                for (int i = 0; i < 4; i++)
                    Cq[(tyl * 4 + i) * 17 + txl] =
                        make_float4(acc[i][0], acc[i][1], acc[i][2], acc[i][3]);
            }
            __syncthreads();

            // ---- sum 4 quarters ----
            const float* Cb = Cmb + gjb * CMBP + gj;
#pragma unroll
            for (int q = 0; q < 4; q++) {
                const float* Cq = Cb + q * 16 * CMBP;
                sc += Cq[0];
                si += Cq[16];
                sf += Cq[32];
                so += Cq[48];
            }
        }

        // ---- gate math ----
        {
            const float a  = tanhf(xc + sc);
            const float ig = sigf(xi + si);
            const float fg = sigf(xf + sf);
            const float og = sigf(xo + so);
            cst = ig * a + fg * cst;
            const float hval = og * tanhf(cst);
            out[((size_t)gb * TT + t) * HH + jglob] = hval;
            g_h[(t + 1) & 1][(size_t)gb * HH + jglob] = hval;
        }

        // ---- grid barrier (proven volatile spin) ----
        __threadfence();
        __syncthreads();
        if (tid == 0) {
            atomicAdd(&g_bar, 1u);
            const unsigned tgt = (unsigned)(t + 1) * (unsigned)NBLK;
            while (*reinterpret_cast<volatile unsigned*>(&g_bar) < tgt) { }
        }
        __syncthreads();
    }
}

// =====================================================================
extern "C" void kernel_launch(void* const* d_in, const int* in_sizes, int n_in,
                              void* d_out, int out_size)
{
    const float* x  = (const float*)d_in[0];
    const float* Wc = (const float*)d_in[1];
    const float* Wi = (const float*)d_in[2];
    const float* Wf = (const float*)d_in[3];
    const float* Wo = (const float*)d_in[4];
    const float* Uc = (const float*)d_in[5];
    const float* Ui = (const float*)d_in[6];
    const float* Uf = (const float*)d_in[7];
    const float* Uo = (const float*)d_in[8];
    const float* bc = (const float*)d_in[9];
    const float* bi = (const float*)d_in[10];
    const float* bf = (const float*)d_in[11];
    const float* bo = (const float*)d_in[12];
    float* out = (float*)d_out;

    cudaFuncSetAttribute(lstm_recur,
                         cudaFuncAttributeMaxDynamicSharedMemorySize, SMEM_BYTES);

    void* barp = nullptr;
    cudaGetSymbolAddress(&barp, g_bar);
    cudaMemsetAsync(barp, 0, sizeof(unsigned int), 0);

    dim3 g1(G4 / 64, (BB * TT) / 64);   // 32 x 1024
    xproj_gemm<<<g1, 256>>>(x, Wc, Wi, Wf, Wo, bc, bi, bf, bo);

    lstm_recur<<<NBLK, THR, SMEM_BYTES>>>(Uc, Ui, Uf, Uo, out);
}

// round 8
// speedup vs baseline: 1.1188x; 1.0829x over previous
#include <cuda_runtime.h>
#include <cuda_bf16.h>
#include <cstdint>
#include <cmath>

#define BB   64      // batch
#define TT   1024    // timesteps
#define DD   512     // input dim
#define HH   512     // hidden dim
#define G4   2048    // 4*H
#define NBLK 128     // persistent blocks

// ---------------- scratch ----------------
__device__ float g_xp[(size_t)TT * BB * G4];   // [T][B][4H]
__device__ float g_h[2][(size_t)BB * HH];      // double-buffered h
__device__ unsigned int g_bar;

// =====================================================================
// Phase 1: xproj GEMM (proven version, unchanged).
// =====================================================================
__global__ void __launch_bounds__(256) xproj_gemm(
    const float* __restrict__ x,
    const float* __restrict__ Wc, const float* __restrict__ Wi,
    const float* __restrict__ Wf, const float* __restrict__ Wo,
    const float* __restrict__ bc, const float* __restrict__ bi,
    const float* __restrict__ bf, const float* __restrict__ bo)
{
    __shared__ float As[16][68];
    __shared__ float Bs[16][64];

    const int tid = threadIdx.x;
    const int n0  = blockIdx.x * 64;
    const int g   = n0 >> 9;
    const int col0 = n0 & 511;
    const int m0  = blockIdx.y * 64;

    const float* Wg = (g == 0) ? Wc : (g == 1) ? Wi : (g == 2) ? Wf : Wo;
    const float* bg = (g == 0) ? bc : (g == 1) ? bi : (g == 2) ? bf : bo;

    const int tx = tid & 15;
    const int ty = tid >> 4;

    float acc[4][4];
#pragma unroll
    for (int u = 0; u < 4; u++)
#pragma unroll
        for (int v = 0; v < 4; v++) acc[u][v] = 0.f;

    const int arow = tid >> 2;
    const int akq  = tid & 3;
    const int bkr  = tid >> 4;
    const int bnq  = tid & 15;

    for (int k0 = 0; k0 < DD; k0 += 16) {
        {
            const float4 v = *reinterpret_cast<const float4*>(
                x + (size_t)(m0 + arow) * DD + k0 + akq * 4);
            As[akq * 4 + 0][arow] = v.x;
            As[akq * 4 + 1][arow] = v.y;
            As[akq * 4 + 2][arow] = v.z;
            As[akq * 4 + 3][arow] = v.w;
        }
        {
            const float4 v = *reinterpret_cast<const float4*>(
                Wg + (size_t)(k0 + bkr) * HH + col0 + bnq * 4);
            *reinterpret_cast<float4*>(&Bs[bkr][bnq * 4]) = v;
        }
        __syncthreads();
#pragma unroll
        for (int kk = 0; kk < 16; kk++) {
            const float4 a4 = *reinterpret_cast<const float4*>(&As[kk][ty * 4]);
            const float4 b4 = *reinterpret_cast<const float4*>(&Bs[kk][tx * 4]);
            const float av[4] = {a4.x, a4.y, a4.z, a4.w};
            const float bv[4] = {b4.x, b4.y, b4.z, b4.w};
#pragma unroll
            for (int u = 0; u < 4; u++)
#pragma unroll
                for (int v = 0; v < 4; v++)
                    acc[u][v] = fmaf(av[u], bv[v], acc[u][v]);
        }
        __syncthreads();
    }

    const float4 bb4 = *reinterpret_cast<const float4*>(bg + col0 + tx * 4);
#pragma unroll
    for (int u = 0; u < 4; u++) {
        const int r  = m0 + ty * 4 + u;
        const int b_ = r >> 10;
        const int t_ = r & 1023;
        float4 o;
        o.x = acc[u][0] + bb4.x;
        o.y = acc[u][1] + bb4.y;
        o.z = acc[u][2] + bb4.z;
        o.w = acc[u][3] + bb4.w;
        *reinterpret_cast<float4*>(
            g_xp + ((size_t)t_ * BB + b_) * G4 + g * HH + col0 + tx * 4) = o;
    }
}

// =====================================================================
// Phase 2: persistent recurrence.
// 512 threads, 8-way k-split -> 4 warps per SMSP for latency hiding.
// 128 blocks = 4 batch-groups(16) x 32 j-groups(16 cols x 4 gates).
// smem: Us[512][64] k-major, hs[512][HSP] transposed h, Cmb[8][16][68].
// Thread (kq 0..7, tyl, txl): 4b x 4c microtile over 64 k.
// Gate math: threads 0..255, one (b, j) pair each, c in register.
// =====================================================================
#define THR     512
#define HSP     20
#define CMBP    68
#define SMEM_BYTES ((512*64 + 512*HSP + 8*16*CMBP) * 4)   // 206,848

__device__ __forceinline__ float sigf(float v) {
    return 1.f / (1.f + __expf(-v));
}

__global__ void __launch_bounds__(THR, 1) lstm_recur(
    const float* __restrict__ Uc, const float* __restrict__ Ui,
    const float* __restrict__ Uf, const float* __restrict__ Uo,
    float* __restrict__ out)
{
    extern __shared__ float sm[];
    float* Us  = sm;                    // [512][64]
    float* hs  = sm + 512 * 64;         // [512][HSP]
    float* Cmb = hs + 512 * HSP;        // [8][16][CMBP]

    const int tid  = threadIdx.x;
    const int bx   = blockIdx.x;
    const int b0   = (bx >> 5) * 16;
    const int jcol0 = (bx & 31) * 16;

    // ---- load resident U slice: Us[k][gate*16+jc] ----
    {
        const int c4   = tid & 15;
        const int gate = c4 >> 2;
        const float* Ug = (gate == 0) ? Uc : (gate == 1) ? Ui
                        : (gate == 2) ? Uf : Uo;
        const float* src = Ug + jcol0 + (c4 & 3) * 4;
        for (int k = tid >> 4; k < 512; k += 32)
            *reinterpret_cast<float4*>(&Us[k * 64 + c4 * 4]) =
                *reinterpret_cast<const float4*>(src + (size_t)k * HH);
    }

    // microtile identity: 8 k-slices of 64
    const int kq  = tid >> 6;          // 0..7
    const int lcl = tid & 63;
    const int txl = lcl & 15;          // 4 cols: txl*4..+3
    const int tyl = lcl >> 4;          // 4 batches: tyl*4..+3
    const int k0q = kq * 64;

    // staging identity
    const int sb = tid & 15;
    const int sq = tid >> 4;           // 0..31

    // gate identity: threads 0..255 own one (b, j) pair
    const int gjb   = (tid >> 4) & 15; // 0..15
    const int gj    = tid & 15;
    const int gb    = b0 + gjb;
    const int jglob = jcol0 + gj;
    const bool gate_owner = (tid < 256);

    const float4* Us4 = reinterpret_cast<const float4*>(Us);

    float cst = 0.f;

    __syncthreads();

    for (int t = 0; t < TT; t++) {
        float xc = 0.f, xi = 0.f, xf = 0.f, xo = 0.f;
        if (gate_owner) {
            const float* xp = g_xp + ((size_t)t * BB + gb) * G4 + jglob;
            xc = xp[0];
            xi = xp[HH];
            xf = xp[2 * HH];
            xo = xp[3 * HH];
        }

        float sc = 0.f, si = 0.f, sf = 0.f, so = 0.f;

        if (t > 0) {
            // ---- stage h(t-1) transposed: hs[k][b] ----
            const float* hb = g_h[t & 1] + (size_t)(b0 + sb) * HH;
#pragma unroll
            for (int it = 0; it < 4; it++) {
                const int kb = (sq + it * 32) * 4;
                const float4 v = __ldcg(reinterpret_cast<const float4*>(hb + kb));
                hs[(kb + 0) * HSP + sb] = v.x;
                hs[(kb + 1) * HSP + sb] = v.y;
                hs[(kb + 2) * HSP + sb] = v.z;
                hs[(kb + 3) * HSP + sb] = v.w;
            }
            __syncthreads();

            float acc[4][4];
#pragma unroll
            for (int i = 0; i < 4; i++)
#pragma unroll
                for (int j = 0; j < 4; j++) acc[i][j] = 0.f;

#pragma unroll 4
            for (int k = k0q; k < k0q + 64; k++) {
                const float4 hv = *reinterpret_cast<const float4*>(
                    &hs[k * HSP + tyl * 4]);
                const float4 uv = Us4[k * 16 + txl];
                const float av[4] = {hv.x, hv.y, hv.z, hv.w};
                const float bv[4] = {uv.x, uv.y, uv.z, uv.w};
#pragma unroll
                for (int i = 0; i < 4; i++)
#pragma unroll
                    for (int j = 0; j < 4; j++)
                        acc[i][j] = fmaf(av[i], bv[j], acc[i][j]);
            }

            // ---- write per-slice partials ----
            {
                float4* Cq = reinterpret_cast<float4*>(Cmb + kq * 16 * CMBP);
#pragma unroll
                for (int i = 0; i < 4; i++)
                    Cq[(tyl * 4 + i) * 17 + txl] =
                        make_float4(acc[i][0], acc[i][1], acc[i][2], acc[i][3]);
            }
            __syncthreads();

            // ---- gate threads sum 8 slices ----
            if (gate_owner) {
                const float* Cb = Cmb + gjb * CMBP + gj;
#pragma unroll
                for (int q = 0; q < 8; q++) {
                    const float* Cq = Cb + q * 16 * CMBP;
                    sc += Cq[0];
                    si += Cq[16];
                    sf += Cq[32];
                    so += Cq[48];
                }
            }
        }

        // ---- gate math ----
        if (gate_owner) {
            const float a  = tanhf(xc + sc);
            const float ig = sigf(xi + si);
            const float fg = sigf(xf + sf);
            const float og = sigf(xo + so);
            cst = ig * a + fg * cst;
            const float hval = og * tanhf(cst);
            out[((size_t)gb * TT + t) * HH + jglob] = hval;
            g_h[(t + 1) & 1][(size_t)gb * HH + jglob] = hval;
        }

        // ---- grid barrier (proven volatile spin) ----
        __threadfence();
        __syncthreads();
        if (tid == 0) {
            atomicAdd(&g_bar, 1u);
            const unsigned tgt = (unsigned)(t + 1) * (unsigned)NBLK;
            while (*reinterpret_cast<volatile unsigned*>(&g_bar) < tgt) { }
        }
        __syncthreads();
    }
}

// =====================================================================
extern "C" void kernel_launch(void* const* d_in, const int* in_sizes, int n_in,
                              void* d_out, int out_size)
{
    const float* x  = (const float*)d_in[0];
    const float* Wc = (const float*)d_in[1];
    const float* Wi = (const float*)d_in[2];
    const float* Wf = (const float*)d_in[3];
    const float* Wo = (const float*)d_in[4];
    const float* Uc = (const float*)d_in[5];
    const float* Ui = (const float*)d_in[6];
    const float* Uf = (const float*)d_in[7];
    const float* Uo = (const float*)d_in[8];
    const float* bc = (const float*)d_in[9];
    const float* bi = (const float*)d_in[10];
    const float* bf = (const float*)d_in[11];
    const float* bo = (const float*)d_in[12];
    float* out = (float*)d_out;

    cudaFuncSetAttribute(lstm_recur,
                         cudaFuncAttributeMaxDynamicSharedMemorySize, SMEM_BYTES);

    void* barp = nullptr;
    cudaGetSymbolAddress(&barp, g_bar);
    cudaMemsetAsync(barp, 0, sizeof(unsigned int), 0);

    dim3 g1(G4 / 64, (BB * TT) / 64);   // 32 x 1024
    xproj_gemm<<<g1, 256>>>(x, Wc, Wi, Wf, Wo, bc, bi, bf, bo);

    lstm_recur<<<NBLK, THR, SMEM_BYTES>>>(Uc, Ui, Uf, Uo, out);
}

// round 9
// speedup vs baseline: 1.3833x; 1.2364x over previous
#include <cuda_runtime.h>
#include <cuda_bf16.h>
#include <cstdint>
#include <cmath>

#define BB   64      // batch
#define TT   1024    // timesteps
#define DD   512     // input dim
#define HH   512     // hidden dim
#define G4   2048    // 4*H
#define NBLK 128     // persistent blocks

// ---------------- scratch ----------------
__device__ float g_xp[(size_t)TT * BB * G4];   // [T][B][4H]
__device__ float g_h[2][(size_t)BB * HH];      // double-buffered h
__device__ unsigned int g_bar;

// =====================================================================
// Phase 1: xproj GEMM (proven version, unchanged).
// =====================================================================
__global__ void __launch_bounds__(256) xproj_gemm(
    const float* __restrict__ x,
    const float* __restrict__ Wc, const float* __restrict__ Wi,
    const float* __restrict__ Wf, const float* __restrict__ Wo,
    const float* __restrict__ bc, const float* __restrict__ bi,
    const float* __restrict__ bf, const float* __restrict__ bo)
{
    __shared__ float As[16][68];
    __shared__ float Bs[16][64];

    const int tid = threadIdx.x;
    const int n0  = blockIdx.x * 64;
    const int g   = n0 >> 9;
    const int col0 = n0 & 511;
    const int m0  = blockIdx.y * 64;

    const float* Wg = (g == 0) ? Wc : (g == 1) ? Wi : (g == 2) ? Wf : Wo;
    const float* bg = (g == 0) ? bc : (g == 1) ? bi : (g == 2) ? bf : bo;

    const int tx = tid & 15;
    const int ty = tid >> 4;

    float acc[4][4];
#pragma unroll
    for (int u = 0; u < 4; u++)
#pragma unroll
        for (int v = 0; v < 4; v++) acc[u][v] = 0.f;

    const int arow = tid >> 2;
    const int akq  = tid & 3;
    const int bkr  = tid >> 4;
    const int bnq  = tid & 15;

    for (int k0 = 0; k0 < DD; k0 += 16) {
        {
            const float4 v = *reinterpret_cast<const float4*>(
                x + (size_t)(m0 + arow) * DD + k0 + akq * 4);
            As[akq * 4 + 0][arow] = v.x;
            As[akq * 4 + 1][arow] = v.y;
            As[akq * 4 + 2][arow] = v.z;
            As[akq * 4 + 3][arow] = v.w;
        }
        {
            const float4 v = *reinterpret_cast<const float4*>(
                Wg + (size_t)(k0 + bkr) * HH + col0 + bnq * 4);
            *reinterpret_cast<float4*>(&Bs[bkr][bnq * 4]) = v;
        }
        __syncthreads();
#pragma unroll
        for (int kk = 0; kk < 16; kk++) {
            const float4 a4 = *reinterpret_cast<const float4*>(&As[kk][ty * 4]);
            const float4 b4 = *reinterpret_cast<const float4*>(&Bs[kk][tx * 4]);
            const float av[4] = {a4.x, a4.y, a4.z, a4.w};
            const float bv[4] = {b4.x, b4.y, b4.z, b4.w};
#pragma unroll
            for (int u = 0; u < 4; u++)
#pragma unroll
                for (int v = 0; v < 4; v++)
                    acc[u][v] = fmaf(av[u], bv[v], acc[u][v]);
        }
        __syncthreads();
    }

    const float4 bb4 = *reinterpret_cast<const float4*>(bg + col0 + tx * 4);
#pragma unroll
    for (int u = 0; u < 4; u++) {
        const int r  = m0 + ty * 4 + u;
        const int b_ = r >> 10;
        const int t_ = r & 1023;
        float4 o;
        o.x = acc[u][0] + bb4.x;
        o.y = acc[u][1] + bb4.y;
        o.z = acc[u][2] + bb4.z;
        o.w = acc[u][3] + bb4.w;
        *reinterpret_cast<float4*>(
            g_xp + ((size_t)t_ * BB + b_) * G4 + g * HH + col0 + tx * 4) = o;
    }
}

// =====================================================================
// Phase 2: persistent recurrence with warp-level TF32 mma.sync.
// 128 blocks = 4 batch-groups(16) x 32 j-groups(16 cols x 4 gates).
// GEMM per block per step: D[64 cols][16 b] = sum_k U[k][64c] * h[k][16b].
// M = cols (64 -> 4 m16 tiles), N = batch (16 -> 2 n8 tiles), K = 512
// split 8 ways over 8 warps (64 k each = 8 k8 tiles).
// U pre-rounded to TF32 (round-to-nearest) in smem once; h split exactly
// h = h1 + h2 (both TF32) at use, two MMA passes into separate accums.
// Combine 8 k-slice partials in smem; gate math on all 256 threads.
// =====================================================================
#define THR     256
#define UPI     72              // Us pitch (floats) -> A-frag loads bank-disjoint
#define HSP     20              // hs pitch (floats)
#define CMBP    65
#define SMEM_FLOATS (512 * UPI + 512 * HSP + 8 * 16 * CMBP)
#define SMEM_BYTES  (SMEM_FLOATS * 4)     // 221,696 B

__device__ __forceinline__ float sigf(float v) {
    return 1.f / (1.f + __expf(-v));
}

__device__ __forceinline__ float to_tf32(float x) {
    float r;
    asm("cvt.rna.tf32.f32 %0, %1;" : "=f"(r) : "f"(x));
    return r;
}

__device__ __forceinline__ void mma_tf32(float* d,
                                         const float* a,
                                         float b0, float b1) {
    asm volatile(
        "mma.sync.aligned.m16n8k8.row.col.f32.tf32.tf32.f32 "
        "{%0,%1,%2,%3},{%4,%5,%6,%7},{%8,%9},{%0,%1,%2,%3};"
        : "+f"(d[0]), "+f"(d[1]), "+f"(d[2]), "+f"(d[3])
        : "r"(__float_as_uint(a[0])), "r"(__float_as_uint(a[1])),
          "r"(__float_as_uint(a[2])), "r"(__float_as_uint(a[3])),
          "r"(__float_as_uint(b0)),  "r"(__float_as_uint(b1)));
}

__global__ void __launch_bounds__(THR, 1) lstm_recur(
    const float* __restrict__ Uc, const float* __restrict__ Ui,
    const float* __restrict__ Uf, const float* __restrict__ Uo,
    float* __restrict__ out)
{
    extern __shared__ float sm[];
    float* Us  = sm;                    // [512][UPI]  TF32-rounded U, k-major
    float* hs  = sm + 512 * UPI;        // [512][HSP]  transposed h (fp32)
    float* Cmb = hs + 512 * HSP;        // [8][16][CMBP]

    const int tid  = threadIdx.x;
    const int bx   = blockIdx.x;
    const int b0   = (bx >> 5) * 16;
    const int jcol0 = (bx & 31) * 16;

    // ---- load resident U slice, pre-rounded to TF32 ----
    {
        const int c4   = tid & 15;
        const int gate = c4 >> 2;
        const float* Ug = (gate == 0) ? Uc : (gate == 1) ? Ui
                        : (gate == 2) ? Uf : Uo;
        const float* src = Ug + jcol0 + (c4 & 3) * 4;
        for (int k = tid >> 4; k < 512; k += 16) {
            float4 v = *reinterpret_cast<const float4*>(src + (size_t)k * HH);
            v.x = to_tf32(v.x);
            v.y = to_tf32(v.y);
            v.z = to_tf32(v.z);
            v.w = to_tf32(v.w);
            *reinterpret_cast<float4*>(&Us[k * UPI + c4 * 4]) = v;
        }
    }

    // warp identity
    const int wid  = tid >> 5;        // 0..7 -> k-slice of 64
    const int lane = tid & 31;
    const int gid  = lane >> 2;       // 0..7
    const int tig  = lane & 3;        // 0..3
    const int kw0  = wid * 64;

    // staging identity
    const int sb = tid & 15;
    const int sq = tid >> 4;          // 0..15

    // gate identity (all 256 threads)
    const int gjb   = tid >> 4;       // 0..15
    const int gj    = tid & 15;
    const int gb    = b0 + gjb;
    const int jglob = jcol0 + gj;

    float cst = 0.f;

    __syncthreads();

    for (int t = 0; t < TT; t++) {
        const float* xp = g_xp + ((size_t)t * BB + gb) * G4 + jglob;
        const float xc = xp[0];
        const float xi = xp[HH];
        const float xf = xp[2 * HH];
        const float xo = xp[3 * HH];

        float sc = 0.f, si = 0.f, sf = 0.f, so = 0.f;

        if (t > 0) {
            // ---- stage h(t-1) transposed: hs[k][b], fp32 ----
            const float* hb = g_h[t & 1] + (size_t)(b0 + sb) * HH;
#pragma unroll
            for (int it = 0; it < 8; it++) {
                const int kb = (sq + it * 16) * 4;
                const float4 v = __ldcg(reinterpret_cast<const float4*>(hb + kb));
                hs[(kb + 0) * HSP + sb] = v.x;
                hs[(kb + 1) * HSP + sb] = v.y;
                hs[(kb + 2) * HSP + sb] = v.z;
                hs[(kb + 3) * HSP + sb] = v.w;
            }
            __syncthreads();

            // ---- TF32 MMA over this warp's 64-k slice ----
            float da[4][2][4];   // h1 pass accumulators [mt][nt][4]
            float db[4][2][4];   // h2 pass
#pragma unroll
            for (int mt = 0; mt < 4; mt++)
#pragma unroll
                for (int nt = 0; nt < 2; nt++)
#pragma unroll
                    for (int r = 0; r < 4; r++) {
                        da[mt][nt][r] = 0.f;
                        db[mt][nt][r] = 0.f;
                    }

#pragma unroll
            for (int kt = 0; kt < 8; kt++) {
                const int kk = kw0 + kt * 8;

                // B fragments: h fp32 -> exact split h1 + h2 (both TF32)
                float b1[2][2], b2[2][2];
#pragma unroll
                for (int nt = 0; nt < 2; nt++) {
                    const int bcol = nt * 8 + gid;
                    const float hv0 = hs[(kk + tig) * HSP + bcol];
                    const float hv1 = hs[(kk + tig + 4) * HSP + bcol];
                    b1[nt][0] = to_tf32(hv0);
                    b1[nt][1] = to_tf32(hv1);
                    b2[nt][0] = to_tf32(hv0 - b1[nt][0]);
                    b2[nt][1] = to_tf32(hv1 - b1[nt][1]);
                }

                // A fragments per m-tile and both passes of MMA
#pragma unroll
                for (int mt = 0; mt < 4; mt++) {
                    const int m0 = mt * 16;
                    float a[4];
                    a[0] = Us[(kk + tig) * UPI + m0 + gid];
                    a[1] = Us[(kk + tig) * UPI + m0 + gid + 8];
                    a[2] = Us[(kk + tig + 4) * UPI + m0 + gid];
                    a[3] = Us[(kk + tig + 4) * UPI + m0 + gid + 8];
#pragma unroll
                    for (int nt = 0; nt < 2; nt++) {
                        mma_tf32(da[mt][nt], a, b1[nt][0], b1[nt][1]);
                        mma_tf32(db[mt][nt], a, b2[nt][0], b2[nt][1]);
                    }
                }
            }

            // ---- write partials: D[col][batch] -> Cmb[wid][b][col] ----
            {
                float* Cq = Cmb + wid * 16 * CMBP;
#pragma unroll
                for (int mt = 0; mt < 4; mt++) {
                    const int j0 = mt * 16 + gid;
#pragma unroll
                    for (int nt = 0; nt < 2; nt++) {
                        const int bb_ = nt * 8 + 2 * tig;
                        Cq[(bb_ + 0) * CMBP + j0]     = da[mt][nt][0] + db[mt][nt][0];
                        Cq[(bb_ + 1) * CMBP + j0]     = da[mt][nt][1] + db[mt][nt][1];
                        Cq[(bb_ + 0) * CMBP + j0 + 8] = da[mt][nt][2] + db[mt][nt][2];
                        Cq[(bb_ + 1) * CMBP + j0 + 8] = da[mt][nt][3] + db[mt][nt][3];
                    }
                }
            }
            __syncthreads();

            // ---- sum 8 k-slice partials ----
            const float* Cb = Cmb + gjb * CMBP + gj;
#pragma unroll
            for (int q = 0; q < 8; q++) {
                const float* Cq = Cb + q * 16 * CMBP;
                sc += Cq[0];
                si += Cq[16];
                sf += Cq[32];
                so += Cq[48];
            }
        }

        // ---- gate math ----
        {
            const float a  = tanhf(xc + sc);
            const float ig = sigf(xi + si);
            const float fg = sigf(xf + sf);
            const float og = sigf(xo + so);
            cst = ig * a + fg * cst;
            const float hval = og * tanhf(cst);
            out[((size_t)gb * TT + t) * HH + jglob] = hval;
            g_h[(t + 1) & 1][(size_t)gb * HH + jglob] = hval;
        }

        // ---- grid barrier (proven volatile spin) ----
        __threadfence();
        __syncthreads();
        if (tid == 0) {
            atomicAdd(&g_bar, 1u);
            const unsigned tgt = (unsigned)(t + 1) * (unsigned)NBLK;
            while (*reinterpret_cast<volatile unsigned*>(&g_bar) < tgt) { }
        }
        __syncthreads();
    }
}

// =====================================================================
extern "C" void kernel_launch(void* const* d_in, const int* in_sizes, int n_in,
                              void* d_out, int out_size)
{
    const float* x  = (const float*)d_in[0];
    const float* Wc = (const float*)d_in[1];
    const float* Wi = (const float*)d_in[2];
    const float* Wf = (const float*)d_in[3];
    const float* Wo = (const float*)d_in[4];
    const float* Uc = (const float*)d_in[5];
    const float* Ui = (const float*)d_in[6];
    const float* Uf = (const float*)d_in[7];
    const float* Uo = (const float*)d_in[8];
    const float* bc = (const float*)d_in[9];
    const float* bi = (const float*)d_in[10];
    const float* bf = (const float*)d_in[11];
    const float* bo = (const float*)d_in[12];
    float* out = (float*)d_out;

    cudaFuncSetAttribute(lstm_recur,
                         cudaFuncAttributeMaxDynamicSharedMemorySize, SMEM_BYTES);

    void* barp = nullptr;
    cudaGetSymbolAddress(&barp, g_bar);
    cudaMemsetAsync(barp, 0, sizeof(unsigned int), 0);

    dim3 g1(G4 / 64, (BB * TT) / 64);   // 32 x 1024
    xproj_gemm<<<g1, 256>>>(x, Wc, Wi, Wf, Wo, bc, bi, bf, bo);

    lstm_recur<<<NBLK, THR, SMEM_BYTES>>>(Uc, Ui, Uf, Uo, out);
}

// round 10
// speedup vs baseline: 1.8195x; 1.3153x over previous
#include <cuda_runtime.h>
#include <cuda_bf16.h>
#include <cstdint>
#include <cmath>

#define BB   64      // batch
#define TT   1024    // timesteps
#define DD   512     // input dim
#define HH   512     // hidden dim
#define G4   2048    // 4*H
#define NBLK 128     // persistent blocks

// ---------------- scratch ----------------
__device__ float g_xp[(size_t)TT * BB * G4];   // [T][B][4H]
__device__ float g_h[2][(size_t)BB * HH];      // double-buffered h
__device__ unsigned int g_bar;

__device__ __forceinline__ float sigf(float v) {
    return 1.f / (1.f + __expf(-v));
}

__device__ __forceinline__ float to_tf32(float x) {
    float r;
    asm("cvt.rna.tf32.f32 %0, %1;" : "=f"(r) : "f"(x));
    return r;
}

__device__ __forceinline__ void mma_tf32(float* d,
                                         const float* a,
                                         float b0, float b1) {
    asm volatile(
        "mma.sync.aligned.m16n8k8.row.col.f32.tf32.tf32.f32 "
        "{%0,%1,%2,%3},{%4,%5,%6,%7},{%8,%9},{%0,%1,%2,%3};"
        : "+f"(d[0]), "+f"(d[1]), "+f"(d[2]), "+f"(d[3])
        : "r"(__float_as_uint(a[0])), "r"(__float_as_uint(a[1])),
          "r"(__float_as_uint(a[2])), "r"(__float_as_uint(a[3])),
          "r"(__float_as_uint(b0)),  "r"(__float_as_uint(b1)));
}

// =====================================================================
// Phase 1: xproj GEMM on TF32 tensor cores.
// C[M=65536, N=2048] = x[M,512] @ W[512,N] + b.
// Block tile 128x128, 256 threads = 8 warps (4 m-warps x 2 n-warps),
// warp tile 32x64 = 2 m16 x 8 n8 MMA tiles. K chunk 32.
// x, W TF32-rounded at smem-store time. Output scattered to [T][B][4H].
// =====================================================================
#define XPI 136
#define XPROJ_SMEM_BYTES (2 * 32 * XPI * 4)   // xs + ws = 34,816 B

__global__ void __launch_bounds__(256) xproj_mma(
    const float* __restrict__ x,
    const float* __restrict__ Wc, const float* __restrict__ Wi,
    const float* __restrict__ Wf, const float* __restrict__ Wo,
    const float* __restrict__ bc, const float* __restrict__ bi,
    const float* __restrict__ bf, const float* __restrict__ bo)
{
    extern __shared__ float xsm[];
    float* xs = xsm;              // [32 k][XPI m]
    float* ws = xsm + 32 * XPI;   // [32 k][XPI n]

    const int tid = threadIdx.x;
    const int n0  = blockIdx.x * 128;       // global gate-col base (0..1920)
    const int m0  = blockIdx.y * 128;
    const int g   = n0 >> 9;
    const int col0 = n0 & 511;

    const float* Wg = (g == 0) ? Wc : (g == 1) ? Wi : (g == 2) ? Wf : Wo;
    const float* bg = (g == 0) ? bc : (g == 1) ? bi : (g == 2) ? bf : bo;

    const int wid  = tid >> 5;
    const int lane = tid & 31;
    const int gid  = lane >> 2;         // 0..7
    const int tig  = lane & 3;          // 0..3
    const int mw0  = (wid & 3) * 32;    // warp m offset in tile
    const int nw0  = (wid >> 2) * 64;   // warp n offset in tile

    float acc[2][8][4];
#pragma unroll
    for (int mt = 0; mt < 2; mt++)
#pragma unroll
        for (int nt = 0; nt < 8; nt++)
#pragma unroll
            for (int r = 0; r < 4; r++) acc[mt][nt][r] = 0.f;

    for (int k0 = 0; k0 < DD; k0 += 32) {
        // ---- stage x tile transposed: xs[k][m], TF32-rounded ----
#pragma unroll
        for (int it = 0; it < 4; it++) {
            const int e   = it * 256 + tid;     // 0..1023
            const int row = e >> 3;             // 0..127
            const int kq  = e & 7;              // float4 chunk in 32-k
            const float4 v = *reinterpret_cast<const float4*>(
                x + (size_t)(m0 + row) * DD + k0 + kq * 4);
            xs[(kq * 4 + 0) * XPI + row] = to_tf32(v.x);
            xs[(kq * 4 + 1) * XPI + row] = to_tf32(v.y);
            xs[(kq * 4 + 2) * XPI + row] = to_tf32(v.z);
            xs[(kq * 4 + 3) * XPI + row] = to_tf32(v.w);
        }
        // ---- stage W tile: ws[k][n], TF32-rounded ----
#pragma unroll
        for (int it = 0; it < 4; it++) {
            const int e  = it * 256 + tid;      // 0..1023
            const int kr = e >> 5;              // 0..31
            const int nq = e & 31;              // float4 along n
            const float4 v = *reinterpret_cast<const float4*>(
                Wg + (size_t)(k0 + kr) * HH + col0 + nq * 4);
            ws[kr * XPI + nq * 4 + 0] = to_tf32(v.x);
            ws[kr * XPI + nq * 4 + 1] = to_tf32(v.y);
            ws[kr * XPI + nq * 4 + 2] = to_tf32(v.z);
            ws[kr * XPI + nq * 4 + 3] = to_tf32(v.w);
        }
        __syncthreads();

#pragma unroll
        for (int kt = 0; kt < 4; kt++) {
            const int kk = kt * 8;

            float b[8][2];
#pragma unroll
            for (int nt = 0; nt < 8; nt++) {
                const int nn = nw0 + nt * 8 + gid;
                b[nt][0] = ws[(kk + tig) * XPI + nn];
                b[nt][1] = ws[(kk + tig + 4) * XPI + nn];
            }
#pragma unroll
            for (int mt = 0; mt < 2; mt++) {
                const int mm = mw0 + mt * 16 + gid;
                float a[4];
                a[0] = xs[(kk + tig) * XPI + mm];
                a[1] = xs[(kk + tig) * XPI + mm + 8];
                a[2] = xs[(kk + tig + 4) * XPI + mm];
                a[3] = xs[(kk + tig + 4) * XPI + mm + 8];
#pragma unroll
                for (int nt = 0; nt < 8; nt++)
                    mma_tf32(acc[mt][nt], a, b[nt][0], b[nt][1]);
            }
        }
        __syncthreads();
    }

    // ---- epilogue: +bias, scatter to g_xp[T][B][4H] ----
#pragma unroll
    for (int nt = 0; nt < 8; nt++) {
        const int cl = col0 + nw0 + nt * 8 + 2 * tig;   // column in gate
        const float2 bb = *reinterpret_cast<const float2*>(bg + cl);
#pragma unroll
        for (int mt = 0; mt < 2; mt++) {
            const int r0 = m0 + mw0 + mt * 16 + gid;
            const int r1 = r0 + 8;
            const int b0_ = r0 >> 10, t0_ = r0 & 1023;
            const int b1_ = r1 >> 10, t1_ = r1 & 1023;
            float* p0 = g_xp + ((size_t)t0_ * BB + b0_) * G4 + g * HH + cl;
            float* p1 = g_xp + ((size_t)t1_ * BB + b1_) * G4 + g * HH + cl;
            *reinterpret_cast<float2*>(p0) =
                make_float2(acc[mt][nt][0] + bb.x, acc[mt][nt][1] + bb.y);
            *reinterpret_cast<float2*>(p1) =
                make_float2(acc[mt][nt][2] + bb.x, acc[mt][nt][3] + bb.y);
        }
    }
}

// =====================================================================
// Phase 2: persistent recurrence with warp-level TF32 mma.sync
// (round-9 proven version, unchanged).
// =====================================================================
#define THR     256
#define UPI     72
#define HSP     20
#define CMBP    65
#define SMEM_FLOATS (512 * UPI + 512 * HSP + 8 * 16 * CMBP)
#define SMEM_BYTES  (SMEM_FLOATS * 4)     // 221,696 B

__global__ void __launch_bounds__(THR, 1) lstm_recur(
    const float* __restrict__ Uc, const float* __restrict__ Ui,
    const float* __restrict__ Uf, const float* __restrict__ Uo,
    float* __restrict__ out)
{
    extern __shared__ float sm[];
    float* Us  = sm;                    // [512][UPI]
    float* hs  = sm + 512 * UPI;        // [512][HSP]
    float* Cmb = hs + 512 * HSP;        // [8][16][CMBP]

    const int tid  = threadIdx.x;
    const int bx   = blockIdx.x;
    const int b0   = (bx >> 5) * 16;
    const int jcol0 = (bx & 31) * 16;

    {
        const int c4   = tid & 15;
        const int gate = c4 >> 2;
        const float* Ug = (gate == 0) ? Uc : (gate == 1) ? Ui
                        : (gate == 2) ? Uf : Uo;
        const float* src = Ug + jcol0 + (c4 & 3) * 4;
        for (int k = tid >> 4; k < 512; k += 16) {
            float4 v = *reinterpret_cast<const float4*>(src + (size_t)k * HH);
            v.x = to_tf32(v.x);
            v.y = to_tf32(v.y);
            v.z = to_tf32(v.z);
            v.w = to_tf32(v.w);
            *reinterpret_cast<float4*>(&Us[k * UPI + c4 * 4]) = v;
        }
    }

    const int wid  = tid >> 5;
    const int lane = tid & 31;
    const int gid  = lane >> 2;
    const int tig  = lane & 3;
    const int kw0  = wid * 64;

    const int sb = tid & 15;
    const int sq = tid >> 4;

    const int gjb   = tid >> 4;
    const int gj    = tid & 15;
    const int gb    = b0 + gjb;
    const int jglob = jcol0 + gj;

    float cst = 0.f;

    __syncthreads();

    for (int t = 0; t < TT; t++) {
        const float* xp = g_xp + ((size_t)t * BB + gb) * G4 + jglob;
        const float xc = xp[0];
        const float xi = xp[HH];
        const float xf = xp[2 * HH];
        const float xo = xp[3 * HH];

        float sc = 0.f, si = 0.f, sf = 0.f, so = 0.f;

        if (t > 0) {
            const float* hb = g_h[t & 1] + (size_t)(b0 + sb) * HH;
#pragma unroll
            for (int it = 0; it < 8; it++) {
                const int kb = (sq + it * 16) * 4;
                const float4 v = __ldcg(reinterpret_cast<const float4*>(hb + kb));
                hs[(kb + 0) * HSP + sb] = v.x;
                hs[(kb + 1) * HSP + sb] = v.y;
                hs[(kb + 2) * HSP + sb] = v.z;
                hs[(kb + 3) * HSP + sb] = v.w;
            }
            __syncthreads();

            float da[4][2][4];
            float db[4][2][4];
#pragma unroll
            for (int mt = 0; mt < 4; mt++)
#pragma unroll
                for (int nt = 0; nt < 2; nt++)
#pragma unroll
                    for (int r = 0; r < 4; r++) {
                        da[mt][nt][r] = 0.f;
                        db[mt][nt][r] = 0.f;
                    }

#pragma unroll
            for (int kt = 0; kt < 8; kt++) {
                const int kk = kw0 + kt * 8;

                float b1[2][2], b2[2][2];
#pragma unroll
                for (int nt = 0; nt < 2; nt++) {
                    const int bcol = nt * 8 + gid;
                    const float hv0 = hs[(kk + tig) * HSP + bcol];
                    const float hv1 = hs[(kk + tig + 4) * HSP + bcol];
                    b1[nt][0] = to_tf32(hv0);
                    b1[nt][1] = to_tf32(hv1);
                    b2[nt][0] = to_tf32(hv0 - b1[nt][0]);
                    b2[nt][1] = to_tf32(hv1 - b1[nt][1]);
                }

#pragma unroll
                for (int mt = 0; mt < 4; mt++) {
                    const int m0 = mt * 16;
                    float a[4];
                    a[0] = Us[(kk + tig) * UPI + m0 + gid];
                    a[1] = Us[(kk + tig) * UPI + m0 + gid + 8];
                    a[2] = Us[(kk + tig + 4) * UPI + m0 + gid];
                    a[3] = Us[(kk + tig + 4) * UPI + m0 + gid + 8];
#pragma unroll
                    for (int nt = 0; nt < 2; nt++) {
                        mma_tf32(da[mt][nt], a, b1[nt][0], b1[nt][1]);
                        mma_tf32(db[mt][nt], a, b2[nt][0], b2[nt][1]);
                    }
                }
            }

            {
                float* Cq = Cmb + wid * 16 * CMBP;
#pragma unroll
                for (int mt = 0; mt < 4; mt++) {
                    const int j0 = mt * 16 + gid;
#pragma unroll
                    for (int nt = 0; nt < 2; nt++) {
                        const int bb_ = nt * 8 + 2 * tig;
                        Cq[(bb_ + 0) * CMBP + j0]     = da[mt][nt][0] + db[mt][nt][0];
                        Cq[(bb_ + 1) * CMBP + j0]     = da[mt][nt][1] + db[mt][nt][1];
                        Cq[(bb_ + 0) * CMBP + j0 + 8] = da[mt][nt][2] + db[mt][nt][2];
                        Cq[(bb_ + 1) * CMBP + j0 + 8] = da[mt][nt][3] + db[mt][nt][3];
                    }
                }
            }
            __syncthreads();

            const float* Cb = Cmb + gjb * CMBP + gj;
#pragma unroll
            for (int q = 0; q < 8; q++) {
                const float* Cq = Cb + q * 16 * CMBP;
                sc += Cq[0];
                si += Cq[16];
                sf += Cq[32];
                so += Cq[48];
            }
        }

        {
            const float a  = tanhf(xc + sc);
            const float ig = sigf(xi + si);
            const float fg = sigf(xf + sf);
            const float og = sigf(xo + so);
            cst = ig * a + fg * cst;
            const float hval = og * tanhf(cst);
            out[((size_t)gb * TT + t) * HH + jglob] = hval;
            g_h[(t + 1) & 1][(size_t)gb * HH + jglob] = hval;
        }

        __threadfence();
        __syncthreads();
        if (tid == 0) {
            atomicAdd(&g_bar, 1u);
            const unsigned tgt = (unsigned)(t + 1) * (unsigned)NBLK;
            while (*reinterpret_cast<volatile unsigned*>(&g_bar) < tgt) { }
        }
        __syncthreads();
    }
}

// =====================================================================
extern "C" void kernel_launch(void* const* d_in, const int* in_sizes, int n_in,
                              void* d_out, int out_size)
{
    const float* x  = (const float*)d_in[0];
    const float* Wc = (const float*)d_in[1];
    const float* Wi = (const float*)d_in[2];
    const float* Wf = (const float*)d_in[3];
    const float* Wo = (const float*)d_in[4];
    const float* Uc = (const float*)d_in[5];
    const float* Ui = (const float*)d_in[6];
    const float* Uf = (const float*)d_in[7];
    const float* Uo = (const float*)d_in[8];
    const float* bc = (const float*)d_in[9];
    const float* bi = (const float*)d_in[10];
    const float* bf = (const float*)d_in[11];
    const float* bo = (const float*)d_in[12];
    float* out = (float*)d_out;

    cudaFuncSetAttribute(lstm_recur,
                         cudaFuncAttributeMaxDynamicSharedMemorySize, SMEM_BYTES);
    cudaFuncSetAttribute(xproj_mma,
                         cudaFuncAttributeMaxDynamicSharedMemorySize, XPROJ_SMEM_BYTES);

    void* barp = nullptr;
    cudaGetSymbolAddress(&barp, g_bar);
    cudaMemsetAsync(barp, 0, sizeof(unsigned int), 0);

    dim3 g1(G4 / 128, (BB * TT) / 128);   // 16 x 512
    xproj_mma<<<g1, 256, XPROJ_SMEM_BYTES>>>(x, Wc, Wi, Wf, Wo, bc, bi, bf, bo);

    lstm_recur<<<NBLK, THR, SMEM_BYTES>>>(Uc, Ui, Uf, Uo, out);
}

// round 11
// speedup vs baseline: 1.8252x; 1.0031x over previous
#include <cuda_runtime.h>
#include <cuda_bf16.h>
#include <cstdint>
#include <cmath>

#define BB   64      // batch
#define TT   1024    // timesteps
#define DD   512     // input dim
#define HH   512     // hidden dim
#define G4   2048    // 4*H
#define NBLK 128     // persistent blocks

// ---------------- scratch ----------------
__device__ float g_xp[(size_t)TT * BB * G4];   // [T][B][4H]
__device__ float g_h[2][(size_t)BB * HH];      // double-buffered h
__device__ unsigned int g_bar;

__device__ __forceinline__ float sigf(float v) {
    return 1.f / (1.f + __expf(-v));
}

__device__ __forceinline__ float ftanh(float v) {
    // tanh(x) = 1 - 2/(exp(2x)+1); accurate to ~1e-6, MUFU-based
    const float e = __expf(2.f * v);
    return 1.f - __fdividef(2.f, e + 1.f);
}

__device__ __forceinline__ float to_tf32(float x) {
    float r;
    asm("cvt.rna.tf32.f32 %0, %1;" : "=f"(r) : "f"(x));
    return r;
}

__device__ __forceinline__ void mma_tf32(float* d,
                                         const float* a,
                                         float b0, float b1) {
    asm volatile(
        "mma.sync.aligned.m16n8k8.row.col.f32.tf32.tf32.f32 "
        "{%0,%1,%2,%3},{%4,%5,%6,%7},{%8,%9},{%0,%1,%2,%3};"
        : "+f"(d[0]), "+f"(d[1]), "+f"(d[2]), "+f"(d[3])
        : "r"(__float_as_uint(a[0])), "r"(__float_as_uint(a[1])),
          "r"(__float_as_uint(a[2])), "r"(__float_as_uint(a[3])),
          "r"(__float_as_uint(b0)),  "r"(__float_as_uint(b1)));
}

// =====================================================================
// Phase 1: xproj GEMM on TF32 tensor cores (round-10 proven, unchanged).
// =====================================================================
#define XPI 136
#define XPROJ_SMEM_BYTES (2 * 32 * XPI * 4)

__global__ void __launch_bounds__(256) xproj_mma(
    const float* __restrict__ x,
    const float* __restrict__ Wc, const float* __restrict__ Wi,
    const float* __restrict__ Wf, const float* __restrict__ Wo,
    const float* __restrict__ bc, const float* __restrict__ bi,
    const float* __restrict__ bf, const float* __restrict__ bo)
{
    extern __shared__ float xsm[];
    float* xs = xsm;              // [32 k][XPI m]
    float* ws = xsm + 32 * XPI;   // [32 k][XPI n]

    const int tid = threadIdx.x;
    const int n0  = blockIdx.x * 128;
    const int m0  = blockIdx.y * 128;
    const int g   = n0 >> 9;
    const int col0 = n0 & 511;

    const float* Wg = (g == 0) ? Wc : (g == 1) ? Wi : (g == 2) ? Wf : Wo;
    const float* bg = (g == 0) ? bc : (g == 1) ? bi : (g == 2) ? bf : bo;

    const int wid  = tid >> 5;
    const int lane = tid & 31;
    const int gid  = lane >> 2;
    const int tig  = lane & 3;
    const int mw0  = (wid & 3) * 32;
    const int nw0  = (wid >> 2) * 64;

    float acc[2][8][4];
#pragma unroll
    for (int mt = 0; mt < 2; mt++)
#pragma unroll
        for (int nt = 0; nt < 8; nt++)
#pragma unroll
            for (int r = 0; r < 4; r++) acc[mt][nt][r] = 0.f;

    for (int k0 = 0; k0 < DD; k0 += 32) {
#pragma unroll
        for (int it = 0; it < 4; it++) {
            const int e   = it * 256 + tid;
            const int row = e >> 3;
            const int kq  = e & 7;
            const float4 v = *reinterpret_cast<const float4*>(
                x + (size_t)(m0 + row) * DD + k0 + kq * 4);
            xs[(kq * 4 + 0) * XPI + row] = to_tf32(v.x);
            xs[(kq * 4 + 1) * XPI + row] = to_tf32(v.y);
            xs[(kq * 4 + 2) * XPI + row] = to_tf32(v.z);
            xs[(kq * 4 + 3) * XPI + row] = to_tf32(v.w);
        }
#pragma unroll
        for (int it = 0; it < 4; it++) {
            const int e  = it * 256 + tid;
            const int kr = e >> 5;
            const int nq = e & 31;
            const float4 v = *reinterpret_cast<const float4*>(
                Wg + (size_t)(k0 + kr) * HH + col0 + nq * 4);
            ws[kr * XPI + nq * 4 + 0] = to_tf32(v.x);
            ws[kr * XPI + nq * 4 + 1] = to_tf32(v.y);
            ws[kr * XPI + nq * 4 + 2] = to_tf32(v.z);
            ws[kr * XPI + nq * 4 + 3] = to_tf32(v.w);
        }
        __syncthreads();

#pragma unroll
        for (int kt = 0; kt < 4; kt++) {
            const int kk = kt * 8;

            float b[8][2];
#pragma unroll
            for (int nt = 0; nt < 8; nt++) {
                const int nn = nw0 + nt * 8 + gid;
                b[nt][0] = ws[(kk + tig) * XPI + nn];
                b[nt][1] = ws[(kk + tig + 4) * XPI + nn];
            }
#pragma unroll
            for (int mt = 0; mt < 2; mt++) {
                const int mm = mw0 + mt * 16 + gid;
                float a[4];
                a[0] = xs[(kk + tig) * XPI + mm];
                a[1] = xs[(kk + tig) * XPI + mm + 8];
                a[2] = xs[(kk + tig + 4) * XPI + mm];
                a[3] = xs[(kk + tig + 4) * XPI + mm + 8];
#pragma unroll
                for (int nt = 0; nt < 8; nt++)
                    mma_tf32(acc[mt][nt], a, b[nt][0], b[nt][1]);
            }
        }
        __syncthreads();
    }

#pragma unroll
    for (int nt = 0; nt < 8; nt++) {
        const int cl = col0 + nw0 + nt * 8 + 2 * tig;
        const float2 bb = *reinterpret_cast<const float2*>(bg + cl);
#pragma unroll
        for (int mt = 0; mt < 2; mt++) {
            const int r0 = m0 + mw0 + mt * 16 + gid;
            const int r1 = r0 + 8;
            const int b0_ = r0 >> 10, t0_ = r0 & 1023;
            const int b1_ = r1 >> 10, t1_ = r1 & 1023;
            float* p0 = g_xp + ((size_t)t0_ * BB + b0_) * G4 + g * HH + cl;
            float* p1 = g_xp + ((size_t)t1_ * BB + b1_) * G4 + g * HH + cl;
            *reinterpret_cast<float2*>(p0) =
                make_float2(acc[mt][nt][0] + bb.x, acc[mt][nt][1] + bb.y);
            *reinterpret_cast<float2*>(p1) =
                make_float2(acc[mt][nt][2] + bb.x, acc[mt][nt][3] + bb.y);
        }
    }
}

// =====================================================================
// Phase 2: persistent recurrence, TF32 mma.sync, NO h staging:
// each warp loads its B fragments (its own 64-k x 16-b h slice)
// directly from global with __ldcg, front-batched into registers.
// 128 blocks = 4 batch-groups(16) x 32 j-groups(16 cols x 4 gates).
// =====================================================================
#define THR     256
#define UPI     72
#define CMBP    65
#define SMEM_FLOATS (512 * UPI + 8 * 16 * CMBP)
#define SMEM_BYTES  (SMEM_FLOATS * 4)     // 180,736 B

__global__ void __launch_bounds__(THR, 1) lstm_recur(
    const float* __restrict__ Uc, const float* __restrict__ Ui,
    const float* __restrict__ Uf, const float* __restrict__ Uo,
    float* __restrict__ out)
{
    extern __shared__ float sm[];
    float* Us  = sm;                    // [512][UPI]  TF32-rounded U
    float* Cmb = sm + 512 * UPI;        // [8][16][CMBP]

    const int tid  = threadIdx.x;
    const int bx   = blockIdx.x;
    const int b0   = (bx >> 5) * 16;
    const int jcol0 = (bx & 31) * 16;

    // ---- load resident U slice, TF32-rounded ----
    {
        const int c4   = tid & 15;
        const int gate = c4 >> 2;
        const float* Ug = (gate == 0) ? Uc : (gate == 1) ? Ui
                        : (gate == 2) ? Uf : Uo;
        const float* src = Ug + jcol0 + (c4 & 3) * 4;
        for (int k = tid >> 4; k < 512; k += 16) {
            float4 v = *reinterpret_cast<const float4*>(src + (size_t)k * HH);
            v.x = to_tf32(v.x);
            v.y = to_tf32(v.y);
            v.z = to_tf32(v.z);
            v.w = to_tf32(v.w);
            *reinterpret_cast<float4*>(&Us[k * UPI + c4 * 4]) = v;
        }
    }

    const int wid  = tid >> 5;        // 0..7 -> k-slice of 64
    const int lane = tid & 31;
    const int gid  = lane >> 2;       // 0..7
    const int tig  = lane & 3;        // 0..3
    const int kw0  = wid * 64;

    // gate identity (all 256 threads)
    const int gjb   = tid >> 4;       // 0..15
    const int gj    = tid & 15;
    const int gb    = b0 + gjb;
    const int jglob = jcol0 + gj;

    // per-warp B-fragment global offsets: rows b0+nt*8+gid, cols kw0+kt*8+tig
    const size_t hoff0 = (size_t)(b0 + gid) * HH + kw0 + tig;      // nt = 0
    const size_t hoff1 = (size_t)(b0 + 8 + gid) * HH + kw0 + tig;  // nt = 1

    float cst = 0.f;

    __syncthreads();

    for (int t = 0; t < TT; t++) {
        const float* xp = g_xp + ((size_t)t * BB + gb) * G4 + jglob;
        const float xc = xp[0];
        const float xi = xp[HH];
        const float xf = xp[2 * HH];
        const float xo = xp[3 * HH];

        float sc = 0.f, si = 0.f, sf = 0.f, so = 0.f;

        if (t > 0) {
            // ---- front-batched B-fragment loads from global h ----
            const float* hb = g_h[t & 1];
            float hv[8][2][2];    // [kt][nt][{tig, tig+4}]
#pragma unroll
            for (int kt = 0; kt < 8; kt++) {
                const float* p0 = hb + hoff0 + kt * 8;
                const float* p1 = hb + hoff1 + kt * 8;
                hv[kt][0][0] = __ldcg(p0);
                hv[kt][0][1] = __ldcg(p0 + 4);
                hv[kt][1][0] = __ldcg(p1);
                hv[kt][1][1] = __ldcg(p1 + 4);
            }

            float da[4][2][4];
            float db[4][2][4];
#pragma unroll
            for (int mt = 0; mt < 4; mt++)
#pragma unroll
                for (int nt = 0; nt < 2; nt++)
#pragma unroll
                    for (int r = 0; r < 4; r++) {
                        da[mt][nt][r] = 0.f;
                        db[mt][nt][r] = 0.f;
                    }

#pragma unroll
            for (int kt = 0; kt < 8; kt++) {
                const int kk = kw0 + kt * 8;

                // exact split h = b1 + b2 (both TF32)
                float b1[2][2], b2[2][2];
#pragma unroll
                for (int nt = 0; nt < 2; nt++) {
                    const float hv0 = hv[kt][nt][0];
                    const float hv1 = hv[kt][nt][1];
                    b1[nt][0] = to_tf32(hv0);
                    b1[nt][1] = to_tf32(hv1);
                    b2[nt][0] = to_tf32(hv0 - b1[nt][0]);
                    b2[nt][1] = to_tf32(hv1 - b1[nt][1]);
                }

#pragma unroll
                for (int mt = 0; mt < 4; mt++) {
                    const int m0 = mt * 16;
                    float a[4];
                    a[0] = Us[(kk + tig) * UPI + m0 + gid];
                    a[1] = Us[(kk + tig) * UPI + m0 + gid + 8];
                    a[2] = Us[(kk + tig + 4) * UPI + m0 + gid];
                    a[3] = Us[(kk + tig + 4) * UPI + m0 + gid + 8];
#pragma unroll
                    for (int nt = 0; nt < 2; nt++) {
                        mma_tf32(da[mt][nt], a, b1[nt][0], b1[nt][1]);
                        mma_tf32(db[mt][nt], a, b2[nt][0], b2[nt][1]);
                    }
                }
            }

            // ---- write k-slice partials ----
            {
                float* Cq = Cmb + wid * 16 * CMBP;
#pragma unroll
                for (int mt = 0; mt < 4; mt++) {
                    const int j0 = mt * 16 + gid;
#pragma unroll
                    for (int nt = 0; nt < 2; nt++) {
                        const int bb_ = nt * 8 + 2 * tig;
                        Cq[(bb_ + 0) * CMBP + j0]     = da[mt][nt][0] + db[mt][nt][0];
                        Cq[(bb_ + 1) * CMBP + j0]     = da[mt][nt][1] + db[mt][nt][1];
                        Cq[(bb_ + 0) * CMBP + j0 + 8] = da[mt][nt][2] + db[mt][nt][2];
                        Cq[(bb_ + 1) * CMBP + j0 + 8] = da[mt][nt][3] + db[mt][nt][3];
                    }
                }
            }
            __syncthreads();

            // ---- sum 8 k-slice partials ----
            const float* Cb = Cmb + gjb * CMBP + gj;
#pragma unroll
            for (int q = 0; q < 8; q++) {
                const float* Cq = Cb + q * 16 * CMBP;
                sc += Cq[0];
                si += Cq[16];
                sf += Cq[32];
                so += Cq[48];
            }
        }

        // ---- gate math ----
        {
            const float a  = ftanh(xc + sc);
            const float ig = sigf(xi + si);
            const float fg = sigf(xf + sf);
            const float og = sigf(xo + so);
            cst = ig * a + fg * cst;
            const float hval = og * ftanh(cst);
            out[((size_t)gb * TT + t) * HH + jglob] = hval;
            g_h[(t + 1) & 1][(size_t)gb * HH + jglob] = hval;
        }

        // ---- grid barrier (proven volatile spin) ----
        __threadfence();
        __syncthreads();
        if (tid == 0) {
            atomicAdd(&g_bar, 1u);
            const unsigned tgt = (unsigned)(t + 1) * (unsigned)NBLK;
            while (*reinterpret_cast<volatile unsigned*>(&g_bar) < tgt) { }
        }
        __syncthreads();
    }
}

// =====================================================================
extern "C" void kernel_launch(void* const* d_in, const int* in_sizes, int n_in,
                              void* d_out, int out_size)
{
    const float* x  = (const float*)d_in[0];
    const float* Wc = (const float*)d_in[1];
    const float* Wi = (const float*)d_in[2];
    const float* Wf = (const float*)d_in[3];
    const float* Wo = (const float*)d_in[4];
    const float* Uc = (const float*)d_in[5];
    const float* Ui = (const float*)d_in[6];
    const float* Uf = (const float*)d_in[7];
    const float* Uo = (const float*)d_in[8];
    const float* bc = (const float*)d_in[9];
    const float* bi = (const float*)d_in[10];
    const float* bf = (const float*)d_in[11];
    const float* bo = (const float*)d_in[12];
    float* out = (float*)d_out;

    cudaFuncSetAttribute(lstm_recur,
                         cudaFuncAttributeMaxDynamicSharedMemorySize, SMEM_BYTES);
    cudaFuncSetAttribute(xproj_mma,
                         cudaFuncAttributeMaxDynamicSharedMemorySize, XPROJ_SMEM_BYTES);

    void* barp = nullptr;
    cudaGetSymbolAddress(&barp, g_bar);
    cudaMemsetAsync(barp, 0, sizeof(unsigned int), 0);

    dim3 g1(G4 / 128, (BB * TT) / 128);   // 16 x 512
    xproj_mma<<<g1, 256, XPROJ_SMEM_BYTES>>>(x, Wc, Wi, Wf, Wo, bc, bi, bf, bo);

    lstm_recur<<<NBLK, THR, SMEM_BYTES>>>(Uc, Ui, Uf, Uo, out);
}

// round 12
// speedup vs baseline: 1.9187x; 1.0513x over previous
#include <cuda_runtime.h>
#include <cuda_bf16.h>
#include <cstdint>
#include <cmath>

#define BB   64      // batch
#define TT   1024    // timesteps
#define DD   512     // input dim
#define HH   512     // hidden dim
#define G4   2048    // 4*H
#define NBLK 128     // persistent blocks
#define GBLK 32      // blocks per batch-group barrier

// ---------------- scratch ----------------
__device__ float g_xp[(size_t)TT * BB * G4];   // [T][B][4H]
__device__ float g_h[2][(size_t)BB * HH];      // double-buffered h
__device__ unsigned int g_barg[4][32];         // per-batch-group counters (128B apart)

__device__ __forceinline__ float sigf(float v) {
    return 1.f / (1.f + __expf(-v));
}

__device__ __forceinline__ float ftanh(float v) {
    const float e = __expf(2.f * v);
    return 1.f - __fdividef(2.f, e + 1.f);
}

__device__ __forceinline__ float to_tf32(float x) {
    float r;
    asm("cvt.rna.tf32.f32 %0, %1;" : "=f"(r) : "f"(x));
    return r;
}

__device__ __forceinline__ void mma_tf32(float* d,
                                         const float* a,
                                         float b0, float b1) {
    asm volatile(
        "mma.sync.aligned.m16n8k8.row.col.f32.tf32.tf32.f32 "
        "{%0,%1,%2,%3},{%4,%5,%6,%7},{%8,%9},{%0,%1,%2,%3};"
        : "+f"(d[0]), "+f"(d[1]), "+f"(d[2]), "+f"(d[3])
        : "r"(__float_as_uint(a[0])), "r"(__float_as_uint(a[1])),
          "r"(__float_as_uint(a[2])), "r"(__float_as_uint(a[3])),
          "r"(__float_as_uint(b0)),  "r"(__float_as_uint(b1)));
}

// =====================================================================
// Phase 1: xproj GEMM on TF32 tensor cores (round-10 proven, unchanged).
// =====================================================================
#define XPI 136
#define XPROJ_SMEM_BYTES (2 * 32 * XPI * 4)

__global__ void __launch_bounds__(256) xproj_mma(
    const float* __restrict__ x,
    const float* __restrict__ Wc, const float* __restrict__ Wi,
    const float* __restrict__ Wf, const float* __restrict__ Wo,
    const float* __restrict__ bc, const float* __restrict__ bi,
    const float* __restrict__ bf, const float* __restrict__ bo)
{
    extern __shared__ float xsm[];
    float* xs = xsm;
    float* ws = xsm + 32 * XPI;

    const int tid = threadIdx.x;
    const int n0  = blockIdx.x * 128;
    const int m0  = blockIdx.y * 128;
    const int g   = n0 >> 9;
    const int col0 = n0 & 511;

    const float* Wg = (g == 0) ? Wc : (g == 1) ? Wi : (g == 2) ? Wf : Wo;
    const float* bg = (g == 0) ? bc : (g == 1) ? bi : (g == 2) ? bf : bo;

    const int wid  = tid >> 5;
    const int lane = tid & 31;
    const int gid  = lane >> 2;
    const int tig  = lane & 3;
    const int mw0  = (wid & 3) * 32;
    const int nw0  = (wid >> 2) * 64;

    float acc[2][8][4];
#pragma unroll
    for (int mt = 0; mt < 2; mt++)
#pragma unroll
        for (int nt = 0; nt < 8; nt++)
#pragma unroll
            for (int r = 0; r < 4; r++) acc[mt][nt][r] = 0.f;

    for (int k0 = 0; k0 < DD; k0 += 32) {
#pragma unroll
        for (int it = 0; it < 4; it++) {
            const int e   = it * 256 + tid;
            const int row = e >> 3;
            const int kq  = e & 7;
            const float4 v = *reinterpret_cast<const float4*>(
                x + (size_t)(m0 + row) * DD + k0 + kq * 4);
            xs[(kq * 4 + 0) * XPI + row] = to_tf32(v.x);
            xs[(kq * 4 + 1) * XPI + row] = to_tf32(v.y);
            xs[(kq * 4 + 2) * XPI + row] = to_tf32(v.z);
            xs[(kq * 4 + 3) * XPI + row] = to_tf32(v.w);
        }
#pragma unroll
        for (int it = 0; it < 4; it++) {
            const int e  = it * 256 + tid;
            const int kr = e >> 5;
            const int nq = e & 31;
            const float4 v = *reinterpret_cast<const float4*>(
                Wg + (size_t)(k0 + kr) * HH + col0 + nq * 4);
            ws[kr * XPI + nq * 4 + 0] = to_tf32(v.x);
            ws[kr * XPI + nq * 4 + 1] = to_tf32(v.y);
            ws[kr * XPI + nq * 4 + 2] = to_tf32(v.z);
            ws[kr * XPI + nq * 4 + 3] = to_tf32(v.w);
        }
        __syncthreads();

#pragma unroll
        for (int kt = 0; kt < 4; kt++) {
            const int kk = kt * 8;

            float b[8][2];
#pragma unroll
            for (int nt = 0; nt < 8; nt++) {
                const int nn = nw0 + nt * 8 + gid;
                b[nt][0] = ws[(kk + tig) * XPI + nn];
                b[nt][1] = ws[(kk + tig + 4) * XPI + nn];
            }
#pragma unroll
            for (int mt = 0; mt < 2; mt++) {
                const int mm = mw0 + mt * 16 + gid;
                float a[4];
                a[0] = xs[(kk + tig) * XPI + mm];
                a[1] = xs[(kk + tig) * XPI + mm + 8];
                a[2] = xs[(kk + tig + 4) * XPI + mm];
                a[3] = xs[(kk + tig + 4) * XPI + mm + 8];
#pragma unroll
                for (int nt = 0; nt < 8; nt++)
                    mma_tf32(acc[mt][nt], a, b[nt][0], b[nt][1]);
            }
        }
        __syncthreads();
    }

#pragma unroll
    for (int nt = 0; nt < 8; nt++) {
        const int cl = col0 + nw0 + nt * 8 + 2 * tig;
        const float2 bb = *reinterpret_cast<const float2*>(bg + cl);
#pragma unroll
        for (int mt = 0; mt < 2; mt++) {
            const int r0 = m0 + mw0 + mt * 16 + gid;
            const int r1 = r0 + 8;
            const int b0_ = r0 >> 10, t0_ = r0 & 1023;
            const int b1_ = r1 >> 10, t1_ = r1 & 1023;
            float* p0 = g_xp + ((size_t)t0_ * BB + b0_) * G4 + g * HH + cl;
            float* p1 = g_xp + ((size_t)t1_ * BB + b1_) * G4 + g * HH + cl;
            *reinterpret_cast<float2*>(p0) =
                make_float2(acc[mt][nt][0] + bb.x, acc[mt][nt][1] + bb.y);
            *reinterpret_cast<float2*>(p1) =
                make_float2(acc[mt][nt][2] + bb.x, acc[mt][nt][3] + bb.y);
        }
    }
}

// =====================================================================
// Phase 2: persistent recurrence, TF32 mma.sync.
// - U stored in A-fragment layout: per (ktg, tig) row of 32 float4
//   frags [mt][gid] (+2 pad), pitch 34 float4 -> conflict-free LDS.128.
// - h B-fragments loaded directly from global (round-11).
// - 4 independent per-batch-group barriers (32 blocks each).
// - out store deferred past the fence (covered by next step's fence).
// =====================================================================
#define THR      256
#define UFP      34                    // float4 pitch per (ktg,tig) row
#define CMBP     65
#define USF4     (256 * UFP)           // 8704 float4
#define SMEM_FLOATS (USF4 * 4 + 8 * 16 * CMBP)
#define SMEM_BYTES  (SMEM_FLOATS * 4)  // 172,544 B

__global__ void __launch_bounds__(THR, 1) lstm_recur(
    const float* __restrict__ Uc, const float* __restrict__ Ui,
    const float* __restrict__ Uf, const float* __restrict__ Uo,
    float* __restrict__ out)
{
    extern __shared__ float sm[];
    float4* Uf4 = reinterpret_cast<float4*>(sm);    // [256 ktig][UFP]
    float*  Cmb = sm + USF4 * 4;                    // [8][16][CMBP]

    const int tid  = threadIdx.x;
    const int bx   = blockIdx.x;
    const int bgrp = bx >> 5;          // batch group 0..3
    const int b0   = bgrp * 16;
    const int jcol0 = (bx & 31) * 16;

    // ---- build A-fragment-layout U in smem (TF32-rounded) ----
    for (int w = tid; w < 8192; w += THR) {
        const int slot = w & 31;           // mt*8 + gid
        const int ktig = w >> 5;           // ktg*4 + tig
        const int mt   = slot >> 3;
        const int gid_ = slot & 7;
        const int tig_ = ktig & 3;
        const int ktg  = ktig >> 2;
        const int k1   = ktg * 8 + tig_;
        const int k2   = k1 + 4;
        const float* Ug = (mt == 0) ? Uc : (mt == 1) ? Ui
                        : (mt == 2) ? Uf : Uo;
        const float* c1 = Ug + jcol0 + gid_;
        float4 v;
        v.x = to_tf32(c1[(size_t)k1 * HH]);
        v.y = to_tf32(c1[(size_t)k1 * HH + 8]);
        v.z = to_tf32(c1[(size_t)k2 * HH]);
        v.w = to_tf32(c1[(size_t)k2 * HH + 8]);
        Uf4[ktig * UFP + slot] = v;
    }

    const int wid  = tid >> 5;        // 0..7 -> k-slice of 64
    const int lane = tid & 31;
    const int gid  = lane >> 2;       // 0..7
    const int tig  = lane & 3;        // 0..3
    const int kw0  = wid * 64;

    // gate identity
    const int gjb   = tid >> 4;       // 0..15
    const int gj    = tid & 15;
    const int gb    = b0 + gjb;
    const int jglob = jcol0 + gj;

    // per-warp B-fragment global offsets
    const size_t hoff0 = (size_t)(b0 + gid) * HH + kw0 + tig;
    const size_t hoff1 = (size_t)(b0 + 8 + gid) * HH + kw0 + tig;

    // per-group barrier counter
    unsigned int* barc = &g_barg[bgrp][0];

    float cst = 0.f;

    __syncthreads();

    for (int t = 0; t < TT; t++) {
        const float* xp = g_xp + ((size_t)t * BB + gb) * G4 + jglob;
        const float xc = xp[0];
        const float xi = xp[HH];
        const float xf = xp[2 * HH];
        const float xo = xp[3 * HH];

        float sc = 0.f, si = 0.f, sf = 0.f, so = 0.f;

        if (t > 0) {
            // ---- front-batched B-fragment loads from global h ----
            const float* hb = g_h[t & 1];
            float hv[8][2][2];
#pragma unroll
            for (int kt = 0; kt < 8; kt++) {
                const float* p0 = hb + hoff0 + kt * 8;
                const float* p1 = hb + hoff1 + kt * 8;
                hv[kt][0][0] = __ldcg(p0);
                hv[kt][0][1] = __ldcg(p0 + 4);
                hv[kt][1][0] = __ldcg(p1);
                hv[kt][1][1] = __ldcg(p1 + 4);
            }

            float da[4][2][4];
            float db[4][2][4];
#pragma unroll
            for (int mt = 0; mt < 4; mt++)
#pragma unroll
                for (int nt = 0; nt < 2; nt++)
#pragma unroll
                    for (int r = 0; r < 4; r++) {
                        da[mt][nt][r] = 0.f;
                        db[mt][nt][r] = 0.f;
                    }

#pragma unroll
            for (int kt = 0; kt < 8; kt++) {
                // exact split h = b1 + b2 (both TF32)
                float b1[2][2], b2[2][2];
#pragma unroll
                for (int nt = 0; nt < 2; nt++) {
                    const float hv0 = hv[kt][nt][0];
                    const float hv1 = hv[kt][nt][1];
                    b1[nt][0] = to_tf32(hv0);
                    b1[nt][1] = to_tf32(hv1);
                    b2[nt][0] = to_tf32(hv0 - b1[nt][0]);
                    b2[nt][1] = to_tf32(hv1 - b1[nt][1]);
                }

                // A fragments: one LDS.128 per mt
                const float4* ap = Uf4 + ((wid * 8 + kt) * 4 + tig) * UFP + gid;
#pragma unroll
                for (int mt = 0; mt < 4; mt++) {
                    const float4 af = ap[mt * 8];
                    const float a[4] = {af.x, af.y, af.z, af.w};
#pragma unroll
                    for (int nt = 0; nt < 2; nt++) {
                        mma_tf32(da[mt][nt], a, b1[nt][0], b1[nt][1]);
                        mma_tf32(db[mt][nt], a, b2[nt][0], b2[nt][1]);
                    }
                }
            }

            // ---- write k-slice partials ----
            {
                float* Cq = Cmb + wid * 16 * CMBP;
#pragma unroll
                for (int mt = 0; mt < 4; mt++) {
                    const int j0 = mt * 16 + gid;
#pragma unroll
                    for (int nt = 0; nt < 2; nt++) {
                        const int bb_ = nt * 8 + 2 * tig;
                        Cq[(bb_ + 0) * CMBP + j0]     = da[mt][nt][0] + db[mt][nt][0];
                        Cq[(bb_ + 1) * CMBP + j0]     = da[mt][nt][1] + db[mt][nt][1];
                        Cq[(bb_ + 0) * CMBP + j0 + 8] = da[mt][nt][2] + db[mt][nt][2];
                        Cq[(bb_ + 1) * CMBP + j0 + 8] = da[mt][nt][3] + db[mt][nt][3];
                    }
                }
            }
            __syncthreads();

            // ---- sum 8 k-slice partials ----
            const float* Cb = Cmb + gjb * CMBP + gj;
#pragma unroll
            for (int q = 0; q < 8; q++) {
                const float* Cq = Cb + q * 16 * CMBP;
                sc += Cq[0];
                si += Cq[16];
                sf += Cq[32];
                so += Cq[48];
            }
        }

        // ---- gate math ----
        const float a  = ftanh(xc + sc);
        const float ig = sigf(xi + si);
        const float fg = sigf(xf + sf);
        const float og = sigf(xo + so);
        cst = ig * a + fg * cst;
        const float hval = og * ftanh(cst);
        g_h[(t + 1) & 1][(size_t)gb * HH + jglob] = hval;

        // ---- per-group barrier: fence h, arrive, deferred out, spin ----
        __threadfence();
        __syncthreads();
        if (tid == 0) atomicAdd(barc, 1u);

        out[((size_t)gb * TT + t) * HH + jglob] = hval;   // off critical chain

        if (tid == 0) {
            const unsigned tgt = (unsigned)(t + 1) * (unsigned)GBLK;
            while (*reinterpret_cast<volatile unsigned*>(barc) < tgt) { }
        }
        __syncthreads();
    }
}

// =====================================================================
extern "C" void kernel_launch(void* const* d_in, const int* in_sizes, int n_in,
                              void* d_out, int out_size)
{
    const float* x  = (const float*)d_in[0];
    const float* Wc = (const float*)d_in[1];
    const float* Wi = (const float*)d_in[2];
    const float* Wf = (const float*)d_in[3];
    const float* Wo = (const float*)d_in[4];
    const float* Uc = (const float*)d_in[5];
    const float* Ui = (const float*)d_in[6];
    const float* Uf = (const float*)d_in[7];
    const float* Uo = (const float*)d_in[8];
    const float* bc = (const float*)d_in[9];
    const float* bi = (const float*)d_in[10];
    const float* bf = (const float*)d_in[11];
    const float* bo = (const float*)d_in[12];
    float* out = (float*)d_out;

    cudaFuncSetAttribute(lstm_recur,
                         cudaFuncAttributeMaxDynamicSharedMemorySize, SMEM_BYTES);
    cudaFuncSetAttribute(xproj_mma,
                         cudaFuncAttributeMaxDynamicSharedMemorySize, XPROJ_SMEM_BYTES);

    void* barp = nullptr;
    cudaGetSymbolAddress(&barp, g_barg);
    cudaMemsetAsync(barp, 0, sizeof(unsigned int) * 4 * 32, 0);

    dim3 g1(G4 / 128, (BB * TT) / 128);   // 16 x 512
    xproj_mma<<<g1, 256, XPROJ_SMEM_BYTES>>>(x, Wc, Wi, Wf, Wo, bc, bi, bf, bo);

    lstm_recur<<<NBLK, THR, SMEM_BYTES>>>(Uc, Ui, Uf, Uo, out);
}

// round 13
// speedup vs baseline: 2.1336x; 1.1120x over previous
#include <cuda_runtime.h>
#include <cuda_bf16.h>
#include <cstdint>
#include <cmath>

#define BB   64      // batch
#define TT   1024    // timesteps
#define DD   512     // input dim
#define HH   512     // hidden dim
#define G4   2048    // 4*H
#define NBLK 128     // persistent blocks
#define GBLK 32      // blocks per batch-group barrier

// ---------------- scratch ----------------
__device__ float g_xp[(size_t)TT * BB * G4];   // [T][B][4H]
__device__ float g_h[2][(size_t)BB * HH];      // double-buffered h
__device__ unsigned int g_barg[4][32];         // per-batch-group counters

__device__ __forceinline__ float sigf(float v) {
    return 1.f / (1.f + __expf(-v));
}

__device__ __forceinline__ float ftanh(float v) {
    const float e = __expf(2.f * v);
    return 1.f - __fdividef(2.f, e + 1.f);
}

__device__ __forceinline__ float to_tf32(float x) {
    float r;
    asm("cvt.rna.tf32.f32 %0, %1;" : "=f"(r) : "f"(x));
    return r;
}

__device__ __forceinline__ void mma_tf32(float* d,
                                         const float* a,
                                         float b0, float b1) {
    asm volatile(
        "mma.sync.aligned.m16n8k8.row.col.f32.tf32.tf32.f32 "
        "{%0,%1,%2,%3},{%4,%5,%6,%7},{%8,%9},{%0,%1,%2,%3};"
        : "+f"(d[0]), "+f"(d[1]), "+f"(d[2]), "+f"(d[3])
        : "r"(__float_as_uint(a[0])), "r"(__float_as_uint(a[1])),
          "r"(__float_as_uint(a[2])), "r"(__float_as_uint(a[3])),
          "r"(__float_as_uint(b0)),  "r"(__float_as_uint(b1)));
}

// =====================================================================
// Phase 1: xproj GEMM on TF32 tensor cores (round-10 proven, unchanged).
// =====================================================================
#define XPI 136
#define XPROJ_SMEM_BYTES (2 * 32 * XPI * 4)

__global__ void __launch_bounds__(256) xproj_mma(
    const float* __restrict__ x,
    const float* __restrict__ Wc, const float* __restrict__ Wi,
    const float* __restrict__ Wf, const float* __restrict__ Wo,
    const float* __restrict__ bc, const float* __restrict__ bi,
    const float* __restrict__ bf, const float* __restrict__ bo)
{
    extern __shared__ float xsm[];
    float* xs = xsm;
    float* ws = xsm + 32 * XPI;

    const int tid = threadIdx.x;
    const int n0  = blockIdx.x * 128;
    const int m0  = blockIdx.y * 128;
    const int g   = n0 >> 9;
    const int col0 = n0 & 511;

    const float* Wg = (g == 0) ? Wc : (g == 1) ? Wi : (g == 2) ? Wf : Wo;
    const float* bg = (g == 0) ? bc : (g == 1) ? bi : (g == 2) ? bf : bo;

    const int wid  = tid >> 5;
    const int lane = tid & 31;
    const int gid  = lane >> 2;
    const int tig  = lane & 3;
    const int mw0  = (wid & 3) * 32;
    const int nw0  = (wid >> 2) * 64;

    float acc[2][8][4];
#pragma unroll
    for (int mt = 0; mt < 2; mt++)
#pragma unroll
        for (int nt = 0; nt < 8; nt++)
#pragma unroll
            for (int r = 0; r < 4; r++) acc[mt][nt][r] = 0.f;

    for (int k0 = 0; k0 < DD; k0 += 32) {
#pragma unroll
        for (int it = 0; it < 4; it++) {
            const int e   = it * 256 + tid;
            const int row = e >> 3;
            const int kq  = e & 7;
            const float4 v = *reinterpret_cast<const float4*>(
                x + (size_t)(m0 + row) * DD + k0 + kq * 4);
            xs[(kq * 4 + 0) * XPI + row] = to_tf32(v.x);
            xs[(kq * 4 + 1) * XPI + row] = to_tf32(v.y);
            xs[(kq * 4 + 2) * XPI + row] = to_tf32(v.z);
            xs[(kq * 4 + 3) * XPI + row] = to_tf32(v.w);
        }
#pragma unroll
        for (int it = 0; it < 4; it++) {
            const int e  = it * 256 + tid;
            const int kr = e >> 5;
            const int nq = e & 31;
            const float4 v = *reinterpret_cast<const float4*>(
                Wg + (size_t)(k0 + kr) * HH + col0 + nq * 4);
            ws[kr * XPI + nq * 4 + 0] = to_tf32(v.x);
            ws[kr * XPI + nq * 4 + 1] = to_tf32(v.y);
            ws[kr * XPI + nq * 4 + 2] = to_tf32(v.z);
            ws[kr * XPI + nq * 4 + 3] = to_tf32(v.w);
        }
        __syncthreads();

#pragma unroll
        for (int kt = 0; kt < 4; kt++) {
            const int kk = kt * 8;

            float b[8][2];
#pragma unroll
            for (int nt = 0; nt < 8; nt++) {
                const int nn = nw0 + nt * 8 + gid;
                b[nt][0] = ws[(kk + tig) * XPI + nn];
                b[nt][1] = ws[(kk + tig + 4) * XPI + nn];
            }
#pragma unroll
            for (int mt = 0; mt < 2; mt++) {
                const int mm = mw0 + mt * 16 + gid;
                float a[4];
                a[0] = xs[(kk + tig) * XPI + mm];
                a[1] = xs[(kk + tig) * XPI + mm + 8];
                a[2] = xs[(kk + tig + 4) * XPI + mm];
                a[3] = xs[(kk + tig + 4) * XPI + mm + 8];
#pragma unroll
                for (int nt = 0; nt < 8; nt++)
                    mma_tf32(acc[mt][nt], a, b[nt][0], b[nt][1]);
            }
        }
        __syncthreads();
    }

#pragma unroll
    for (int nt = 0; nt < 8; nt++) {
        const int cl = col0 + nw0 + nt * 8 + 2 * tig;
        const float2 bb = *reinterpret_cast<const float2*>(bg + cl);
#pragma unroll
        for (int mt = 0; mt < 2; mt++) {
            const int r0 = m0 + mw0 + mt * 16 + gid;
            const int r1 = r0 + 8;
            const int b0_ = r0 >> 10, t0_ = r0 & 1023;
            const int b1_ = r1 >> 10, t1_ = r1 & 1023;
            float* p0 = g_xp + ((size_t)t0_ * BB + b0_) * G4 + g * HH + cl;
            float* p1 = g_xp + ((size_t)t1_ * BB + b1_) * G4 + g * HH + cl;
            *reinterpret_cast<float2*>(p0) =
                make_float2(acc[mt][nt][0] + bb.x, acc[mt][nt][1] + bb.y);
            *reinterpret_cast<float2*>(p1) =
                make_float2(acc[mt][nt][2] + bb.x, acc[mt][nt][3] + bb.y);
        }
    }
}

// =====================================================================
// Phase 2: persistent recurrence, TF32 mma.sync.
// Round-12 structure plus:
//   - single-pass TF32 on h (correction pass dropped; error budget ok)
//   - xp(t+1) prefetched between barrier arrive and spin
// =====================================================================
#define THR      256
#define UFP      34
#define CMBP     65
#define USF4     (256 * UFP)
#define SMEM_FLOATS (USF4 * 4 + 8 * 16 * CMBP)
#define SMEM_BYTES  (SMEM_FLOATS * 4)  // 172,544 B

__global__ void __launch_bounds__(THR, 1) lstm_recur(
    const float* __restrict__ Uc, const float* __restrict__ Ui,
    const float* __restrict__ Uf, const float* __restrict__ Uo,
    float* __restrict__ out)
{
    extern __shared__ float sm[];
    float4* Uf4 = reinterpret_cast<float4*>(sm);    // [256 ktig][UFP]
    float*  Cmb = sm + USF4 * 4;                    // [8][16][CMBP]

    const int tid  = threadIdx.x;
    const int bx   = blockIdx.x;
    const int bgrp = bx >> 5;
    const int b0   = bgrp * 16;
    const int jcol0 = (bx & 31) * 16;

    // ---- build A-fragment-layout U in smem (TF32-rounded) ----
    for (int w = tid; w < 8192; w += THR) {
        const int slot = w & 31;
        const int ktig = w >> 5;
        const int mt   = slot >> 3;
        const int gid_ = slot & 7;
        const int tig_ = ktig & 3;
        const int ktg  = ktig >> 2;
        const int k1   = ktg * 8 + tig_;
        const int k2   = k1 + 4;
        const float* Ug = (mt == 0) ? Uc : (mt == 1) ? Ui
                        : (mt == 2) ? Uf : Uo;
        const float* c1 = Ug + jcol0 + gid_;
        float4 v;
        v.x = to_tf32(c1[(size_t)k1 * HH]);
        v.y = to_tf32(c1[(size_t)k1 * HH + 8]);
        v.z = to_tf32(c1[(size_t)k2 * HH]);
        v.w = to_tf32(c1[(size_t)k2 * HH + 8]);
        Uf4[ktig * UFP + slot] = v;
    }

    const int wid  = tid >> 5;
    const int lane = tid & 31;
    const int gid  = lane >> 2;
    const int tig  = lane & 3;
    const int kw0  = wid * 64;

    const int gjb   = tid >> 4;
    const int gj    = tid & 15;
    const int gb    = b0 + gjb;
    const int jglob = jcol0 + gj;

    const size_t hoff0 = (size_t)(b0 + gid) * HH + kw0 + tig;
    const size_t hoff1 = (size_t)(b0 + 8 + gid) * HH + kw0 + tig;

    unsigned int* barc = &g_barg[bgrp][0];

    float cst = 0.f;

    // xp registers for step 0 (prefetched; later steps load before spin)
    const float* xp0 = g_xp + (size_t)gb * G4 + jglob;
    float xc = __ldcs(xp0);
    float xi = __ldcs(xp0 + HH);
    float xf = __ldcs(xp0 + 2 * HH);
    float xo = __ldcs(xp0 + 3 * HH);

    __syncthreads();

    for (int t = 0; t < TT; t++) {
        float sc = 0.f, si = 0.f, sf = 0.f, so = 0.f;

        if (t > 0) {
            // ---- front-batched B-fragment loads from global h ----
            const float* hb = g_h[t & 1];
            float hv[8][2][2];
#pragma unroll
            for (int kt = 0; kt < 8; kt++) {
                const float* p0 = hb + hoff0 + kt * 8;
                const float* p1 = hb + hoff1 + kt * 8;
                hv[kt][0][0] = __ldcg(p0);
                hv[kt][0][1] = __ldcg(p0 + 4);
                hv[kt][1][0] = __ldcg(p1);
                hv[kt][1][1] = __ldcg(p1 + 4);
            }

            float da[4][2][4];
#pragma unroll
            for (int mt = 0; mt < 4; mt++)
#pragma unroll
                for (int nt = 0; nt < 2; nt++)
#pragma unroll
                    for (int r = 0; r < 4; r++) da[mt][nt][r] = 0.f;

#pragma unroll
            for (int kt = 0; kt < 8; kt++) {
                // single-pass TF32 on h
                float b1[2][2];
#pragma unroll
                for (int nt = 0; nt < 2; nt++) {
                    b1[nt][0] = to_tf32(hv[kt][nt][0]);
                    b1[nt][1] = to_tf32(hv[kt][nt][1]);
                }

                const float4* ap = Uf4 + ((wid * 8 + kt) * 4 + tig) * UFP + gid;
#pragma unroll
                for (int mt = 0; mt < 4; mt++) {
                    const float4 af = ap[mt * 8];
                    const float a[4] = {af.x, af.y, af.z, af.w};
#pragma unroll
                    for (int nt = 0; nt < 2; nt++)
                        mma_tf32(da[mt][nt], a, b1[nt][0], b1[nt][1]);
                }
            }

            // ---- write k-slice partials ----
            {
                float* Cq = Cmb + wid * 16 * CMBP;
#pragma unroll
                for (int mt = 0; mt < 4; mt++) {
                    const int j0 = mt * 16 + gid;
#pragma unroll
                    for (int nt = 0; nt < 2; nt++) {
                        const int bb_ = nt * 8 + 2 * tig;
                        Cq[(bb_ + 0) * CMBP + j0]     = da[mt][nt][0];
                        Cq[(bb_ + 1) * CMBP + j0]     = da[mt][nt][1];
                        Cq[(bb_ + 0) * CMBP + j0 + 8] = da[mt][nt][2];
                        Cq[(bb_ + 1) * CMBP + j0 + 8] = da[mt][nt][3];
                    }
                }
            }
            __syncthreads();

            // ---- sum 8 k-slice partials ----
            const float* Cb = Cmb + gjb * CMBP + gj;
#pragma unroll
            for (int q = 0; q < 8; q++) {
                const float* Cq = Cb + q * 16 * CMBP;
                sc += Cq[0];
                si += Cq[16];
                sf += Cq[32];
                so += Cq[48];
            }
        }

        // ---- gate math ----
        const float a  = ftanh(xc + sc);
        const float ig = sigf(xi + si);
        const float fg = sigf(xf + sf);
        const float og = sigf(xo + so);
        cst = ig * a + fg * cst;
        const float hval = og * ftanh(cst);
        g_h[(t + 1) & 1][(size_t)gb * HH + jglob] = hval;

        // ---- fence h, arrive ----
        __threadfence();
        __syncthreads();
        if (tid == 0) atomicAdd(barc, 1u);

        // ---- off-critical-path work while others arrive ----
        __stcg(out + ((size_t)gb * TT + t) * HH + jglob, hval);
        if (t + 1 < TT) {
            const float* xp = g_xp + ((size_t)(t + 1) * BB + gb) * G4 + jglob;
            xc = __ldcs(xp);
            xi = __ldcs(xp + HH);
            xf = __ldcs(xp + 2 * HH);
            xo = __ldcs(xp + 3 * HH);
        }

        // ---- spin ----
        if (tid == 0) {
            const unsigned tgt = (unsigned)(t + 1) * (unsigned)GBLK;
            while (*reinterpret_cast<volatile unsigned*>(barc) < tgt) { }
        }
        __syncthreads();
    }
}

// =====================================================================
extern "C" void kernel_launch(void* const* d_in, const int* in_sizes, int n_in,
                              void* d_out, int out_size)
{
    const float* x  = (const float*)d_in[0];
    const float* Wc = (const float*)d_in[1];
    const float* Wi = (const float*)d_in[2];
    const float* Wf = (const float*)d_in[3];
    const float* Wo = (const float*)d_in[4];
    const float* Uc = (const float*)d_in[5];
    const float* Ui = (const float*)d_in[6];
    const float* Uf = (const float*)d_in[7];
    const float* Uo = (const float*)d_in[8];
    const float* bc = (const float*)d_in[9];
    const float* bi = (const float*)d_in[10];
    const float* bf = (const float*)d_in[11];
    const float* bo = (const float*)d_in[12];
    float* out = (float*)d_out;

    cudaFuncSetAttribute(lstm_recur,
                         cudaFuncAttributeMaxDynamicSharedMemorySize, SMEM_BYTES);
    cudaFuncSetAttribute(xproj_mma,
                         cudaFuncAttributeMaxDynamicSharedMemorySize, XPROJ_SMEM_BYTES);

    void* barp = nullptr;
    cudaGetSymbolAddress(&barp, g_barg);
    cudaMemsetAsync(barp, 0, sizeof(unsigned int) * 4 * 32, 0);

    dim3 g1(G4 / 128, (BB * TT) / 128);   // 16 x 512
    xproj_mma<<<g1, 256, XPROJ_SMEM_BYTES>>>(x, Wc, Wi, Wf, Wo, bc, bi, bf, bo);

    lstm_recur<<<NBLK, THR, SMEM_BYTES>>>(Uc, Ui, Uf, Uo, out);
}

// round 15
// speedup vs baseline: 2.1912x; 1.0270x over previous
#include <cuda_runtime.h>
#include <cuda_bf16.h>
#include <cstdint>
#include <cmath>

#define BB   64      // batch
#define TT   1024    // timesteps
#define DD   512     // input dim
#define HH   512     // hidden dim
#define G4   2048    // 4*H
#define NBLK 128     // persistent blocks
#define GBLK 32      // blocks per batch-group barrier

// ---------------- scratch ----------------
__device__ float g_xp[(size_t)TT * BB * G4];   // [T][B][4H]
__device__ float g_h[2][(size_t)BB * HH];      // double-buffered h
__device__ unsigned int g_barg[4][32];         // per-batch-group counters

__device__ __forceinline__ float sigf(float v) {
    return 1.f / (1.f + __expf(-v));
}

__device__ __forceinline__ float ftanh(float v) {
    const float e = __expf(2.f * v);
    return 1.f - __fdividef(2.f, e + 1.f);
}

__device__ __forceinline__ float to_tf32(float x) {
    float r;
    asm("cvt.rna.tf32.f32 %0, %1;" : "=f"(r) : "f"(x));
    return r;
}

__device__ __forceinline__ void mma_tf32(float* d,
                                         const float* a,
                                         float b0, float b1) {
    asm volatile(
        "mma.sync.aligned.m16n8k8.row.col.f32.tf32.tf32.f32 "
        "{%0,%1,%2,%3},{%4,%5,%6,%7},{%8,%9},{%0,%1,%2,%3};"
        : "+f"(d[0]), "+f"(d[1]), "+f"(d[2]), "+f"(d[3])
        : "r"(__float_as_uint(a[0])), "r"(__float_as_uint(a[1])),
          "r"(__float_as_uint(a[2])), "r"(__float_as_uint(a[3])),
          "r"(__float_as_uint(b0)),  "r"(__float_as_uint(b1)));
}

// =====================================================================
// Phase 1: xproj GEMM on TF32 tensor cores (round-10/13 PROVEN version).
// =====================================================================
#define XPI 136
#define XPROJ_SMEM_BYTES (2 * 32 * XPI * 4)

__global__ void __launch_bounds__(256) xproj_mma(
    const float* __restrict__ x,
    const float* __restrict__ Wc, const float* __restrict__ Wi,
    const float* __restrict__ Wf, const float* __restrict__ Wo,
    const float* __restrict__ bc, const float* __restrict__ bi,
    const float* __restrict__ bf, const float* __restrict__ bo)
{
    extern __shared__ float xsm[];
    float* xs = xsm;
    float* ws = xsm + 32 * XPI;

    const int tid = threadIdx.x;
    const int n0  = blockIdx.x * 128;
    const int m0  = blockIdx.y * 128;
    const int g   = n0 >> 9;
    const int col0 = n0 & 511;

    const float* Wg = (g == 0) ? Wc : (g == 1) ? Wi : (g == 2) ? Wf : Wo;
    const float* bg = (g == 0) ? bc : (g == 1) ? bi : (g == 2) ? bf : bo;

    const int wid  = tid >> 5;
    const int lane = tid & 31;
    const int gid  = lane >> 2;
    const int tig  = lane & 3;
    const int mw0  = (wid & 3) * 32;
    const int nw0  = (wid >> 2) * 64;

    float acc[2][8][4];
#pragma unroll
    for (int mt = 0; mt < 2; mt++)
#pragma unroll
        for (int nt = 0; nt < 8; nt++)
#pragma unroll
            for (int r = 0; r < 4; r++) acc[mt][nt][r] = 0.f;

    for (int k0 = 0; k0 < DD; k0 += 32) {
#pragma unroll
        for (int it = 0; it < 4; it++) {
            const int e   = it * 256 + tid;
            const int row = e >> 3;
            const int kq  = e & 7;
            const float4 v = *reinterpret_cast<const float4*>(
                x + (size_t)(m0 + row) * DD + k0 + kq * 4);
            xs[(kq * 4 + 0) * XPI + row] = to_tf32(v.x);
            xs[(kq * 4 + 1) * XPI + row] = to_tf32(v.y);
            xs[(kq * 4 + 2) * XPI + row] = to_tf32(v.z);
            xs[(kq * 4 + 3) * XPI + row] = to_tf32(v.w);
        }
#pragma unroll
        for (int it = 0; it < 4; it++) {
            const int e  = it * 256 + tid;
            const int kr = e >> 5;
            const int nq = e & 31;
            const float4 v = *reinterpret_cast<const float4*>(
                Wg + (size_t)(k0 + kr) * HH + col0 + nq * 4);
            ws[kr * XPI + nq * 4 + 0] = to_tf32(v.x);
            ws[kr * XPI + nq * 4 + 1] = to_tf32(v.y);
            ws[kr * XPI + nq * 4 + 2] = to_tf32(v.z);
            ws[kr * XPI + nq * 4 + 3] = to_tf32(v.w);
        }
        __syncthreads();

#pragma unroll
        for (int kt = 0; kt < 4; kt++) {
            const int kk = kt * 8;

            float b[8][2];
#pragma unroll
            for (int nt = 0; nt < 8; nt++) {
                const int nn = nw0 + nt * 8 + gid;
                b[nt][0] = ws[(kk + tig) * XPI + nn];
                b[nt][1] = ws[(kk + tig + 4) * XPI + nn];
            }
#pragma unroll
            for (int mt = 0; mt < 2; mt++) {
                const int mm = mw0 + mt * 16 + gid;
                float a[4];
                a[0] = xs[(kk + tig) * XPI + mm];
                a[1] = xs[(kk + tig) * XPI + mm + 8];
                a[2] = xs[(kk + tig + 4) * XPI + mm];
                a[3] = xs[(kk + tig + 4) * XPI + mm + 8];
#pragma unroll
                for (int nt = 0; nt < 8; nt++)
                    mma_tf32(acc[mt][nt], a, b[nt][0], b[nt][1]);
            }
        }
        __syncthreads();
    }

#pragma unroll
    for (int nt = 0; nt < 8; nt++) {
        const int cl = col0 + nw0 + nt * 8 + 2 * tig;
        const float2 bb = *reinterpret_cast<const float2*>(bg + cl);
#pragma unroll
        for (int mt = 0; mt < 2; mt++) {
            const int r0 = m0 + mw0 + mt * 16 + gid;
            const int r1 = r0 + 8;
            const int b0_ = r0 >> 10, t0_ = r0 & 1023;
            const int b1_ = r1 >> 10, t1_ = r1 & 1023;
            float* p0 = g_xp + ((size_t)t0_ * BB + b0_) * G4 + g * HH + cl;
            float* p1 = g_xp + ((size_t)t1_ * BB + b1_) * G4 + g * HH + cl;
            *reinterpret_cast<float2*>(p0) =
                make_float2(acc[mt][nt][0] + bb.x, acc[mt][nt][1] + bb.y);
            *reinterpret_cast<float2*>(p1) =
                make_float2(acc[mt][nt][2] + bb.x, acc[mt][nt][3] + bb.y);
        }
    }
}

// =====================================================================
// Phase 2: persistent recurrence (round-13 structure) with a
// release/acquire grid barrier (grid_sync pattern): no __threadfence.
//   h stores -> bar.sync -> tid0 red.release.gpu -> (deferred work)
//   -> tid0 ld.acquire.gpu spin -> bar.sync.
// =====================================================================
#define THR      256
#define UFP      34
#define CMBP     65
#define USF4     (256 * UFP)
#define SMEM_FLOATS (USF4 * 4 + 8 * 16 * CMBP)
#define SMEM_BYTES  (SMEM_FLOATS * 4)  // 172,544 B

__global__ void __launch_bounds__(THR, 1) lstm_recur(
    const float* __restrict__ Uc, const float* __restrict__ Ui,
    const float* __restrict__ Uf, const float* __restrict__ Uo,
    float* __restrict__ out)
{
    extern __shared__ float sm[];
    float4* Uf4 = reinterpret_cast<float4*>(sm);    // [256 ktig][UFP]
    float*  Cmb = sm + USF4 * 4;                    // [8][16][CMBP]

    const int tid  = threadIdx.x;
    const int bx   = blockIdx.x;
    const int bgrp = bx >> 5;
    const int b0   = bgrp * 16;
    const int jcol0 = (bx & 31) * 16;

    // ---- build A-fragment-layout U in smem (TF32-rounded) ----
    for (int w = tid; w < 8192; w += THR) {
        const int slot = w & 31;
        const int ktig = w >> 5;
        const int mt   = slot >> 3;
        const int gid_ = slot & 7;
        const int tig_ = ktig & 3;
        const int ktg  = ktig >> 2;
        const int k1   = ktg * 8 + tig_;
        const int k2   = k1 + 4;
        const float* Ug = (mt == 0) ? Uc : (mt == 1) ? Ui
                        : (mt == 2) ? Uf : Uo;
        const float* c1 = Ug + jcol0 + gid_;
        float4 v;
        v.x = to_tf32(c1[(size_t)k1 * HH]);
        v.y = to_tf32(c1[(size_t)k1 * HH + 8]);
        v.z = to_tf32(c1[(size_t)k2 * HH]);
        v.w = to_tf32(c1[(size_t)k2 * HH + 8]);
        Uf4[ktig * UFP + slot] = v;
    }

    const int wid  = tid >> 5;
    const int lane = tid & 31;
    const int gid  = lane >> 2;
    const int tig  = lane & 3;
    const int kw0  = wid * 64;

    const int gjb   = tid >> 4;
    const int gj    = tid & 15;
    const int gb    = b0 + gjb;
    const int jglob = jcol0 + gj;

    const size_t hoff0 = (size_t)(b0 + gid) * HH + kw0 + tig;
    const size_t hoff1 = (size_t)(b0 + 8 + gid) * HH + kw0 + tig;

    // barrier counter: explicit GLOBAL-space address for the asm ops
    const unsigned long long barg =
        (unsigned long long)__cvta_generic_to_global(&g_barg[bgrp][0]);

    float cst = 0.f;

    const float* xp0 = g_xp + (size_t)gb * G4 + jglob;
    float xc = __ldcs(xp0);
    float xi = __ldcs(xp0 + HH);
    float xf = __ldcs(xp0 + 2 * HH);
    float xo = __ldcs(xp0 + 3 * HH);

    __syncthreads();

    for (int t = 0; t < TT; t++) {
        float sc = 0.f, si = 0.f, sf = 0.f, so = 0.f;

        if (t > 0) {
            const float* hb = g_h[t & 1];
            float hv[8][2][2];
#pragma unroll
            for (int kt = 0; kt < 8; kt++) {
                const float* p0 = hb + hoff0 + kt * 8;
                const float* p1 = hb + hoff1 + kt * 8;
                hv[kt][0][0] = __ldcg(p0);
                hv[kt][0][1] = __ldcg(p0 + 4);
                hv[kt][1][0] = __ldcg(p1);
                hv[kt][1][1] = __ldcg(p1 + 4);
            }

            float da[4][2][4];
#pragma unroll
            for (int mt = 0; mt < 4; mt++)
#pragma unroll
                for (int nt = 0; nt < 2; nt++)
#pragma unroll
                    for (int r = 0; r < 4; r++) da[mt][nt][r] = 0.f;

#pragma unroll
            for (int kt = 0; kt < 8; kt++) {
                float b1[2][2];
#pragma unroll
                for (int nt = 0; nt < 2; nt++) {
                    b1[nt][0] = to_tf32(hv[kt][nt][0]);
                    b1[nt][1] = to_tf32(hv[kt][nt][1]);
                }

                const float4* ap = Uf4 + ((wid * 8 + kt) * 4 + tig) * UFP + gid;
#pragma unroll
                for (int mt = 0; mt < 4; mt++) {
                    const float4 af = ap[mt * 8];
                    const float a[4] = {af.x, af.y, af.z, af.w};
#pragma unroll
                    for (int nt = 0; nt < 2; nt++)
                        mma_tf32(da[mt][nt], a, b1[nt][0], b1[nt][1]);
                }
            }

            {
                float* Cq = Cmb + wid * 16 * CMBP;
#pragma unroll
                for (int mt = 0; mt < 4; mt++) {
                    const int j0 = mt * 16 + gid;
#pragma unroll
                    for (int nt = 0; nt < 2; nt++) {
                        const int bb_ = nt * 8 + 2 * tig;
                        Cq[(bb_ + 0) * CMBP + j0]     = da[mt][nt][0];
                        Cq[(bb_ + 1) * CMBP + j0]     = da[mt][nt][1];
                        Cq[(bb_ + 0) * CMBP + j0 + 8] = da[mt][nt][2];
                        Cq[(bb_ + 1) * CMBP + j0 + 8] = da[mt][nt][3];
                    }
                }
            }
            __syncthreads();

            const float* Cb = Cmb + gjb * CMBP + gj;
#pragma unroll
            for (int q = 0; q < 8; q++) {
                const float* Cq = Cb + q * 16 * CMBP;
                sc += Cq[0];
                si += Cq[16];
                sf += Cq[32];
                so += Cq[48];
            }
        }

        const float a  = ftanh(xc + sc);
        const float ig = sigf(xi + si);
        const float fg = sigf(xf + sf);
        const float og = sigf(xo + so);
        cst = ig * a + fg * cst;
        const float hval = og * ftanh(cst);
        g_h[(t + 1) & 1][(size_t)gb * HH + jglob] = hval;

        // ---- grid barrier: release arrive (no threadfence) ----
        __syncthreads();                 // all h stores happen-before arrive
        if (tid == 0) {
            asm volatile("red.release.gpu.global.add.u32 [%0], %1;"
                         :: "l"(barg), "r"(1u) : "memory");
        }

        // ---- off-critical-path work while siblings arrive ----
        __stcg(out + ((size_t)gb * TT + t) * HH + jglob, hval);
        if (t + 1 < TT) {
            const float* xp = g_xp + ((size_t)(t + 1) * BB + gb) * G4 + jglob;
            xc = __ldcs(xp);
            xi = __ldcs(xp + HH);
            xf = __ldcs(xp + 2 * HH);
            xo = __ldcs(xp + 3 * HH);
        }

        // ---- acquire spin ----
        if (tid == 0) {
            const unsigned tgt = (unsigned)(t + 1) * (unsigned)GBLK;
            unsigned v;
            do {
                asm volatile("ld.acquire.gpu.global.u32 %0, [%1];"
                             : "=r"(v) : "l"(barg) : "memory");
            } while (v < tgt);
        }
        __syncthreads();                 // broadcast acquire to all threads
    }
}

// =====================================================================
extern "C" void kernel_launch(void* const* d_in, const int* in_sizes, int n_in,
                              void* d_out, int out_size)
{
    const float* x  = (const float*)d_in[0];
    const float* Wc = (const float*)d_in[1];
    const float* Wi = (const float*)d_in[2];
    const float* Wf = (const float*)d_in[3];
    const float* Wo = (const float*)d_in[4];
    const float* Uc = (const float*)d_in[5];
    const float* Ui = (const float*)d_in[6];
    const float* Uf = (const float*)d_in[7];
    const float* Uo = (const float*)d_in[8];
    const float* bc = (const float*)d_in[9];
    const float* bi = (const float*)d_in[10];
    const float* bf = (const float*)d_in[11];
    const float* bo = (const float*)d_in[12];
    float* out = (float*)d_out;

    cudaFuncSetAttribute(lstm_recur,
                         cudaFuncAttributeMaxDynamicSharedMemorySize, SMEM_BYTES);
    cudaFuncSetAttribute(xproj_mma,
                         cudaFuncAttributeMaxDynamicSharedMemorySize, XPROJ_SMEM_BYTES);

    void* barp = nullptr;
    cudaGetSymbolAddress(&barp, g_barg);
    cudaMemsetAsync(barp, 0, sizeof(unsigned int) * 4 * 32, 0);

    dim3 g1(G4 / 128, (BB * TT) / 128);   // 16 x 512
    xproj_mma<<<g1, 256, XPROJ_SMEM_BYTES>>>(x, Wc, Wi, Wf, Wo, bc, bi, bf, bo);

    lstm_recur<<<NBLK, THR, SMEM_BYTES>>>(Uc, Ui, Uf, Uo, out);
}